// round 3
// baseline (speedup 1.0000x reference)
#include <cuda_runtime.h>
#include <cstdint>
#include <cstddef>

// ---------------------------------------------------------------------------
// MeshGNN: N=50000, E=600000, IN=16, ED=4, H=128, L=4, OUT=3
// Round 2: packed fma.rn.f32x2 (FFMA2) over the K dimension for all big GEMMs.
// K-pair-interleaved weights in smem => zero pack instructions in inner loop.
// ---------------------------------------------------------------------------

#define N_NODES 50000
#define N_EDGES 600000
#define H 128
#define IN_F 16
#define ED 4
#define KE (H + ED)       // 132
#define N_LAYERS 4
#define N_OUT 3
#define TE 64             // edges per tile
#define TN 32             // nodes per tile

__device__ float g_h[(size_t)N_NODES * H];
__device__ float g_agg[(size_t)N_NODES * H];
__device__ float g_inv[N_NODES];

// packed f32x2 FMA: acc(lo,hi) += a(lo,hi)*b(lo,hi) elementwise
#define FMA2(acc, a, b) \
    asm("fma.rn.f32x2 %0, %1, %2, %0;" : "+l"(acc) : "l"(a), "l"(b))

__device__ __forceinline__ float2 upk(unsigned long long v) {
    float2 r;
    asm("mov.b64 {%0, %1}, %2;" : "=f"(r.x), "=f"(r.y) : "l"(v));
    return r;
}

// ---------------------------------------------------------------------------
// Small helpers
// ---------------------------------------------------------------------------

__global__ void zero_agg_kernel() {
    size_t i = (size_t)blockIdx.x * blockDim.x + threadIdx.x;
    const size_t n4 = (size_t)N_NODES * H / 4;
    float4 z = make_float4(0.f, 0.f, 0.f, 0.f);
    for (; i < n4; i += (size_t)gridDim.x * blockDim.x)
        reinterpret_cast<float4*>(g_agg)[i] = z;
}

__global__ void zero_cnt_kernel() {
    int i = blockIdx.x * blockDim.x + threadIdx.x;
    if (i < N_NODES) g_inv[i] = 0.f;
}

__global__ void deg_kernel(const int* __restrict__ dst) {
    int e = blockIdx.x * blockDim.x + threadIdx.x;
    if (e < N_EDGES) atomicAdd(&g_inv[dst[e]], 1.0f);
}

__global__ void inv_kernel() {
    int i = blockIdx.x * blockDim.x + threadIdx.x;
    if (i < N_NODES) g_inv[i] = 1.0f / fmaxf(g_inv[i], 1.0f);
}

__global__ void lin_in_kernel(const float* __restrict__ x,
                              const float* __restrict__ W,
                              const float* __restrict__ b) {
    __shared__ float sx[IN_F];
    int n = blockIdx.x;
    if (threadIdx.x < IN_F) sx[threadIdx.x] = x[(size_t)n * IN_F + threadIdx.x];
    __syncthreads();
    int c = threadIdx.x;
    float acc = __ldg(&b[c]);
#pragma unroll
    for (int k = 0; k < IN_F; k++)
        acc = fmaf(sx[k], __ldg(&W[k * H + c]), acc);
    g_h[(size_t)n * H + c] = fmaxf(acc, 0.f);
}

// Stage weights into smem in k-pair-interleaved layout:
//   sW[((k/2)*H + c)*2 + (k&1)] = W[k*H + c]
// so that a 64-bit lane holds (W[2kp][c], W[2kp+1][c]).
__device__ __forceinline__ void stage_packed(float* sW, const float* __restrict__ W,
                                             int kdim) {
    for (int i = threadIdx.x; i < kdim * H; i += 256) {
        int k = i >> 7;        // / H (H=128)
        int c = i & 127;
        sW[(((k >> 1) * H + c) << 1) | (k & 1)] = W[i];
    }
}

// ---------------------------------------------------------------------------
// Fused edge MLP + scatter. 256 thr = 8 warps; warp owns 8 edge rows of a
// 64-edge tile. Thread tile: 8 rows x 4 cols. FFMA2 packed over K.
// ---------------------------------------------------------------------------
__global__ void __launch_bounds__(256, 1)
edge_kernel(const int* __restrict__ src, const int* __restrict__ dst,
            const float* __restrict__ ea,
            const float* __restrict__ W1, const float* __restrict__ b1,
            const float* __restrict__ W2, const float* __restrict__ b2) {
    extern __shared__ float sm[];
    float* sW1 = sm;              // KE*H (packed)
    float* sW2 = sW1 + KE * H;    // H*H  (packed)
    float* sA  = sW2 + H * H;     // TE*KE
    float* sM  = sA + TE * KE;    // TE*H

    stage_packed(sW1, W1, KE);
    stage_packed(sW2, W2, H);

    const int lane = threadIdx.x & 31;
    const int w    = threadIdx.x >> 5;
    float b1v[4], b2v[4];
#pragma unroll
    for (int j = 0; j < 4; j++) {
        b1v[j] = __ldg(&b1[lane * 4 + j]);
        b2v[j] = __ldg(&b2[lane * 4 + j]);
    }
    __syncthreads();

    const int ntiles = N_EDGES / TE;
    for (int t = blockIdx.x; t < ntiles; t += gridDim.x) {
        const int e0 = t * TE + w * 8;

        // gather
#pragma unroll
        for (int i = 0; i < 8; i++) {
            int s = __ldg(&src[e0 + i]);
            float4 v = *reinterpret_cast<const float4*>(g_h + (size_t)s * H + lane * 4);
            *reinterpret_cast<float4*>(sA + (w * 8 + i) * KE + lane * 4) = v;
        }
        if (lane < 8) {
            float4 a = *reinterpret_cast<const float4*>(ea + (size_t)(e0 + lane) * ED);
            *reinterpret_cast<float4*>(sA + (w * 8 + lane) * KE + H) = a;
        }
        __syncwarp();

        // GEMM1: [64 x 132] @ [132 x 128], packed-K FFMA2
        unsigned long long acc[8][4];
#pragma unroll
        for (int i = 0; i < 8; i++)
#pragma unroll
            for (int j = 0; j < 4; j++) acc[i][j] = 0ULL;

#pragma unroll 1
        for (int kc = 0; kc < KE; kc += 4) {
            ulonglong2 a2[8];
#pragma unroll
            for (int i = 0; i < 8; i++)
                a2[i] = *reinterpret_cast<const ulonglong2*>(sA + (w * 8 + i) * KE + kc);
            const float* wp = sW1 + (((kc >> 1) * H + lane * 4) << 1);
            ulonglong2 w0 = *reinterpret_cast<const ulonglong2*>(wp);          // kp0: c0,c1
            ulonglong2 w1 = *reinterpret_cast<const ulonglong2*>(wp + 4);      // kp0: c2,c3
            ulonglong2 w2 = *reinterpret_cast<const ulonglong2*>(wp + 2 * H);  // kp1: c0,c1
            ulonglong2 w3 = *reinterpret_cast<const ulonglong2*>(wp + 2 * H + 4);
#pragma unroll
            for (int i = 0; i < 8; i++) {
                FMA2(acc[i][0], a2[i].x, w0.x);
                FMA2(acc[i][1], a2[i].x, w0.y);
                FMA2(acc[i][2], a2[i].x, w1.x);
                FMA2(acc[i][3], a2[i].x, w1.y);
                FMA2(acc[i][0], a2[i].y, w2.x);
                FMA2(acc[i][1], a2[i].y, w2.y);
                FMA2(acc[i][2], a2[i].y, w3.x);
                FMA2(acc[i][3], a2[i].y, w3.y);
            }
        }
#pragma unroll
        for (int i = 0; i < 8; i++) {
            float2 p0 = upk(acc[i][0]), p1 = upk(acc[i][1]);
            float2 p2 = upk(acc[i][2]), p3 = upk(acc[i][3]);
            float4 r = make_float4(fmaxf(p0.x + p0.y + b1v[0], 0.f),
                                   fmaxf(p1.x + p1.y + b1v[1], 0.f),
                                   fmaxf(p2.x + p2.y + b1v[2], 0.f),
                                   fmaxf(p3.x + p3.y + b1v[3], 0.f));
            *reinterpret_cast<float4*>(sM + (w * 8 + i) * H + lane * 4) = r;
        }
        __syncwarp();

        // GEMM2: [64 x 128] @ [128 x 128]
        unsigned long long acc2[8][4];
#pragma unroll
        for (int i = 0; i < 8; i++)
#pragma unroll
            for (int j = 0; j < 4; j++) acc2[i][j] = 0ULL;

#pragma unroll 1
        for (int kc = 0; kc < H; kc += 4) {
            ulonglong2 a2[8];
#pragma unroll
            for (int i = 0; i < 8; i++)
                a2[i] = *reinterpret_cast<const ulonglong2*>(sM + (w * 8 + i) * H + kc);
            const float* wp = sW2 + (((kc >> 1) * H + lane * 4) << 1);
            ulonglong2 w0 = *reinterpret_cast<const ulonglong2*>(wp);
            ulonglong2 w1 = *reinterpret_cast<const ulonglong2*>(wp + 4);
            ulonglong2 w2 = *reinterpret_cast<const ulonglong2*>(wp + 2 * H);
            ulonglong2 w3 = *reinterpret_cast<const ulonglong2*>(wp + 2 * H + 4);
#pragma unroll
            for (int i = 0; i < 8; i++) {
                FMA2(acc2[i][0], a2[i].x, w0.x);
                FMA2(acc2[i][1], a2[i].x, w0.y);
                FMA2(acc2[i][2], a2[i].x, w1.x);
                FMA2(acc2[i][3], a2[i].x, w1.y);
                FMA2(acc2[i][0], a2[i].y, w2.x);
                FMA2(acc2[i][1], a2[i].y, w2.y);
                FMA2(acc2[i][2], a2[i].y, w3.x);
                FMA2(acc2[i][3], a2[i].y, w3.y);
            }
        }

        // scatter relu(C2) into agg[dst]
#pragma unroll
        for (int i = 0; i < 8; i++) {
            int d = __ldg(&dst[e0 + i]);
            float2 p0 = upk(acc2[i][0]), p1 = upk(acc2[i][1]);
            float2 p2 = upk(acc2[i][2]), p3 = upk(acc2[i][3]);
            float4 r = make_float4(fmaxf(p0.x + p0.y + b2v[0], 0.f),
                                   fmaxf(p1.x + p1.y + b2v[1], 0.f),
                                   fmaxf(p2.x + p2.y + b2v[2], 0.f),
                                   fmaxf(p3.x + p3.y + b2v[3], 0.f));
#if __CUDA_ARCH__ >= 900
            atomicAdd(reinterpret_cast<float4*>(g_agg + (size_t)d * H + lane * 4), r);
#else
            float* p = g_agg + (size_t)d * H + lane * 4;
            atomicAdd(p + 0, r.x); atomicAdd(p + 1, r.y);
            atomicAdd(p + 2, r.z); atomicAdd(p + 3, r.w);
#endif
        }
        __syncwarp();
    }
}

// ---------------------------------------------------------------------------
// Node update, packed-K FFMA2. Warp owns 4 node rows; tile 4x4.
// ---------------------------------------------------------------------------
__global__ void __launch_bounds__(256, 1)
node_kernel(const float* __restrict__ W1, const float* __restrict__ b1,
            const float* __restrict__ W2, const float* __restrict__ b2) {
    extern __shared__ float sm[];
    float* sW1 = sm;               // 2H*H packed (k = 0..255)
    float* sW2 = sW1 + 2 * H * H;  // H*H packed
    float* sH  = sW2 + H * H;      // TN*H
    float* sG  = sH + TN * H;      // TN*H (reused as U)

    stage_packed(sW1, W1, 2 * H);
    stage_packed(sW2, W2, H);

    const int lane = threadIdx.x & 31;
    const int w    = threadIdx.x >> 5;
    float b1v[4], b2v[4];
#pragma unroll
    for (int j = 0; j < 4; j++) {
        b1v[j] = __ldg(&b1[lane * 4 + j]);
        b2v[j] = __ldg(&b2[lane * 4 + j]);
    }
    __syncthreads();

    const int ntiles = (N_NODES + TN - 1) / TN;
    for (int t = blockIdx.x; t < ntiles; t += gridDim.x) {
        const int n0 = t * TN + w * 4;

#pragma unroll
        for (int i = 0; i < 4; i++) {
            int n = n0 + i;
            float4 hv = make_float4(0.f, 0.f, 0.f, 0.f);
            float4 gv = make_float4(0.f, 0.f, 0.f, 0.f);
            if (n < N_NODES) {
                hv = *reinterpret_cast<const float4*>(g_h + (size_t)n * H + lane * 4);
                float inv = __ldg(&g_inv[n]);
                float4 g = *reinterpret_cast<const float4*>(g_agg + (size_t)n * H + lane * 4);
                gv = make_float4(g.x * inv, g.y * inv, g.z * inv, g.w * inv);
            }
            *reinterpret_cast<float4*>(sH + (w * 4 + i) * H + lane * 4) = hv;
            *reinterpret_cast<float4*>(sG + (w * 4 + i) * H + lane * 4) = gv;
        }
        __syncwarp();

        // GEMM1 over K=256 (h part then agg part)
        unsigned long long acc[4][4];
#pragma unroll
        for (int i = 0; i < 4; i++)
#pragma unroll
            for (int j = 0; j < 4; j++) acc[i][j] = 0ULL;

#pragma unroll 1
        for (int kc = 0; kc < H; kc += 4) {
            ulonglong2 a2[4];
#pragma unroll
            for (int i = 0; i < 4; i++)
                a2[i] = *reinterpret_cast<const ulonglong2*>(sH + (w * 4 + i) * H + kc);
            const float* wp = sW1 + (((kc >> 1) * H + lane * 4) << 1);
            ulonglong2 w0 = *reinterpret_cast<const ulonglong2*>(wp);
            ulonglong2 w1 = *reinterpret_cast<const ulonglong2*>(wp + 4);
            ulonglong2 w2 = *reinterpret_cast<const ulonglong2*>(wp + 2 * H);
            ulonglong2 w3 = *reinterpret_cast<const ulonglong2*>(wp + 2 * H + 4);
#pragma unroll
            for (int i = 0; i < 4; i++) {
                FMA2(acc[i][0], a2[i].x, w0.x);
                FMA2(acc[i][1], a2[i].x, w0.y);
                FMA2(acc[i][2], a2[i].x, w1.x);
                FMA2(acc[i][3], a2[i].x, w1.y);
                FMA2(acc[i][0], a2[i].y, w2.x);
                FMA2(acc[i][1], a2[i].y, w2.y);
                FMA2(acc[i][2], a2[i].y, w3.x);
                FMA2(acc[i][3], a2[i].y, w3.y);
            }
        }
#pragma unroll 1
        for (int kc = 0; kc < H; kc += 4) {
            ulonglong2 a2[4];
#pragma unroll
            for (int i = 0; i < 4; i++)
                a2[i] = *reinterpret_cast<const ulonglong2*>(sG + (w * 4 + i) * H + kc);
            // second K half: global k = H + kc -> kp = (H + kc)/2
            const float* wp = sW1 + ((((H + kc) >> 1) * H + lane * 4) << 1);
            ulonglong2 w0 = *reinterpret_cast<const ulonglong2*>(wp);
            ulonglong2 w1 = *reinterpret_cast<const ulonglong2*>(wp + 4);
            ulonglong2 w2 = *reinterpret_cast<const ulonglong2*>(wp + 2 * H);
            ulonglong2 w3 = *reinterpret_cast<const ulonglong2*>(wp + 2 * H + 4);
#pragma unroll
            for (int i = 0; i < 4; i++) {
                FMA2(acc[i][0], a2[i].x, w0.x);
                FMA2(acc[i][1], a2[i].x, w0.y);
                FMA2(acc[i][2], a2[i].x, w1.x);
                FMA2(acc[i][3], a2[i].x, w1.y);
                FMA2(acc[i][0], a2[i].y, w2.x);
                FMA2(acc[i][1], a2[i].y, w2.y);
                FMA2(acc[i][2], a2[i].y, w3.x);
                FMA2(acc[i][3], a2[i].y, w3.y);
            }
        }
        __syncwarp();

#pragma unroll
        for (int i = 0; i < 4; i++) {
            float2 p0 = upk(acc[i][0]), p1 = upk(acc[i][1]);
            float2 p2 = upk(acc[i][2]), p3 = upk(acc[i][3]);
            float4 u = make_float4(fmaxf(p0.x + p0.y + b1v[0], 0.f),
                                   fmaxf(p1.x + p1.y + b1v[1], 0.f),
                                   fmaxf(p2.x + p2.y + b1v[2], 0.f),
                                   fmaxf(p3.x + p3.y + b1v[3], 0.f));
            *reinterpret_cast<float4*>(sG + (w * 4 + i) * H + lane * 4) = u;
        }
        __syncwarp();

        // GEMM2 + residual + relu
        unsigned long long acc2[4][4];
#pragma unroll
        for (int i = 0; i < 4; i++)
#pragma unroll
            for (int j = 0; j < 4; j++) acc2[i][j] = 0ULL;

#pragma unroll 1
        for (int kc = 0; kc < H; kc += 4) {
            ulonglong2 a2[4];
#pragma unroll
            for (int i = 0; i < 4; i++)
                a2[i] = *reinterpret_cast<const ulonglong2*>(sG + (w * 4 + i) * H + kc);
            const float* wp = sW2 + (((kc >> 1) * H + lane * 4) << 1);
            ulonglong2 w0 = *reinterpret_cast<const ulonglong2*>(wp);
            ulonglong2 w1 = *reinterpret_cast<const ulonglong2*>(wp + 4);
            ulonglong2 w2 = *reinterpret_cast<const ulonglong2*>(wp + 2 * H);
            ulonglong2 w3 = *reinterpret_cast<const ulonglong2*>(wp + 2 * H + 4);
#pragma unroll
            for (int i = 0; i < 4; i++) {
                FMA2(acc2[i][0], a2[i].x, w0.x);
                FMA2(acc2[i][1], a2[i].x, w0.y);
                FMA2(acc2[i][2], a2[i].x, w1.x);
                FMA2(acc2[i][3], a2[i].x, w1.y);
                FMA2(acc2[i][0], a2[i].y, w2.x);
                FMA2(acc2[i][1], a2[i].y, w2.y);
                FMA2(acc2[i][2], a2[i].y, w3.x);
                FMA2(acc2[i][3], a2[i].y, w3.y);
            }
        }
#pragma unroll
        for (int i = 0; i < 4; i++) {
            int n = n0 + i;
            if (n < N_NODES) {
                float4 hv = *reinterpret_cast<const float4*>(sH + (w * 4 + i) * H + lane * 4);
                float2 p0 = upk(acc2[i][0]), p1 = upk(acc2[i][1]);
                float2 p2 = upk(acc2[i][2]), p3 = upk(acc2[i][3]);
                float4 o = make_float4(fmaxf(p0.x + p0.y + b2v[0] + hv.x, 0.f),
                                       fmaxf(p1.x + p1.y + b2v[1] + hv.y, 0.f),
                                       fmaxf(p2.x + p2.y + b2v[2] + hv.z, 0.f),
                                       fmaxf(p3.x + p3.y + b2v[3] + hv.w, 0.f));
                *reinterpret_cast<float4*>(g_h + (size_t)n * H + lane * 4) = o;
            }
        }
        __syncwarp();
    }
}

// ---------------------------------------------------------------------------
// Head (small: ~2 GFLOP total) — unchanged scalar path.
// ---------------------------------------------------------------------------
__global__ void __launch_bounds__(256, 1)
head_kernel(const float* __restrict__ W1, const float* __restrict__ b1,
            const float* __restrict__ W2, const float* __restrict__ b2,
            float* __restrict__ out) {
    extern __shared__ float sm[];
    float* sW1 = sm;               // H*H
    float* sW2 = sW1 + H * H;      // H*N_OUT
    float* sH  = sW2 + H * N_OUT;  // TN*H

    for (int i = threadIdx.x; i < H * H; i += 256) sW1[i] = W1[i];
    for (int i = threadIdx.x; i < H * N_OUT; i += 256) sW2[i] = W2[i];

    const int lane = threadIdx.x & 31;
    const int w    = threadIdx.x >> 5;
    float b1v[4];
#pragma unroll
    for (int j = 0; j < 4; j++) b1v[j] = __ldg(&b1[lane * 4 + j]);
    const float b2v0 = __ldg(&b2[0]), b2v1 = __ldg(&b2[1]), b2v2 = __ldg(&b2[2]);
    __syncthreads();

    const int ntiles = (N_NODES + TN - 1) / TN;
    for (int t = blockIdx.x; t < ntiles; t += gridDim.x) {
        const int n0 = t * TN + w * 4;
#pragma unroll
        for (int i = 0; i < 4; i++) {
            int n = n0 + i;
            float4 hv = make_float4(0.f, 0.f, 0.f, 0.f);
            if (n < N_NODES)
                hv = *reinterpret_cast<const float4*>(g_h + (size_t)n * H + lane * 4);
            *reinterpret_cast<float4*>(sH + (w * 4 + i) * H + lane * 4) = hv;
        }
        __syncwarp();

        float acc[4][4];
#pragma unroll
        for (int i = 0; i < 4; i++) {
            acc[i][0] = b1v[0]; acc[i][1] = b1v[1];
            acc[i][2] = b1v[2]; acc[i][3] = b1v[3];
        }
#pragma unroll 1
        for (int kc = 0; kc < H; kc += 4) {
            float4 a4[4];
#pragma unroll
            for (int i = 0; i < 4; i++)
                a4[i] = *reinterpret_cast<const float4*>(sH + (w * 4 + i) * H + kc);
#pragma unroll
            for (int kk = 0; kk < 4; kk++) {
                float4 bv = *reinterpret_cast<const float4*>(sW1 + (kc + kk) * H + lane * 4);
#pragma unroll
                for (int i = 0; i < 4; i++) {
                    float a = (kk == 0) ? a4[i].x : (kk == 1) ? a4[i].y
                             : (kk == 2) ? a4[i].z : a4[i].w;
                    acc[i][0] = fmaf(a, bv.x, acc[i][0]);
                    acc[i][1] = fmaf(a, bv.y, acc[i][1]);
                    acc[i][2] = fmaf(a, bv.z, acc[i][2]);
                    acc[i][3] = fmaf(a, bv.w, acc[i][3]);
                }
            }
        }

#pragma unroll
        for (int i = 0; i < 4; i++) {
            float p0 = 0.f, p1 = 0.f, p2 = 0.f;
#pragma unroll
            for (int j = 0; j < 4; j++) {
                float o = fmaxf(acc[i][j], 0.f);
                int kk = lane * 4 + j;
                p0 = fmaf(o, sW2[kk * N_OUT + 0], p0);
                p1 = fmaf(o, sW2[kk * N_OUT + 1], p1);
                p2 = fmaf(o, sW2[kk * N_OUT + 2], p2);
            }
#pragma unroll
            for (int off = 16; off > 0; off >>= 1) {
                p0 += __shfl_xor_sync(0xffffffffu, p0, off);
                p1 += __shfl_xor_sync(0xffffffffu, p1, off);
                p2 += __shfl_xor_sync(0xffffffffu, p2, off);
            }
            int n = n0 + i;
            if (lane == 0 && n < N_NODES) {
                out[(size_t)n * N_OUT + 0] = fmaxf(p0 + b2v0, 0.f);
                out[(size_t)n * N_OUT + 1] = fmaxf(p1 + b2v1, 0.f);
                out[(size_t)n * N_OUT + 2] = fmaxf(p2 + b2v2, 0.f);
            }
        }
        __syncwarp();
    }
}

// ---------------------------------------------------------------------------
extern "C" void kernel_launch(void* const* d_in, const int* in_sizes, int n_in,
                              void* d_out, int out_size) {
    const float* x       = (const float*)d_in[0];
    const int*   ei      = (const int*)d_in[1];
    const float* ea      = (const float*)d_in[2];
    const float* lin_w   = (const float*)d_in[3];
    const float* lin_b   = (const float*)d_in[4];
    const float* msg_w1  = (const float*)d_in[5];
    const float* msg_b1  = (const float*)d_in[6];
    const float* msg_w2  = (const float*)d_in[7];
    const float* msg_b2  = (const float*)d_in[8];
    const float* upd_w1  = (const float*)d_in[9];
    const float* upd_b1  = (const float*)d_in[10];
    const float* upd_w2  = (const float*)d_in[11];
    const float* upd_b2  = (const float*)d_in[12];
    const float* head_w1 = (const float*)d_in[13];
    const float* head_b1 = (const float*)d_in[14];
    const float* head_w2 = (const float*)d_in[15];
    const float* head_b2 = (const float*)d_in[16];
    float* out = (float*)d_out;

    const int* src = ei;
    const int* dst = ei + N_EDGES;

    int sm_count = 148;
    cudaDeviceGetAttribute(&sm_count, cudaDevAttrMultiProcessorCount, 0);

    const size_t smE  = (size_t)(KE * H + H * H + TE * KE + TE * H) * sizeof(float);
    const size_t smN  = (size_t)(2 * H * H + H * H + 2 * TN * H) * sizeof(float);
    const size_t smHd = (size_t)(H * H + H * N_OUT + TN * H) * sizeof(float);
    cudaFuncSetAttribute(edge_kernel, cudaFuncAttributeMaxDynamicSharedMemorySize, (int)smE);
    cudaFuncSetAttribute(node_kernel, cudaFuncAttributeMaxDynamicSharedMemorySize, (int)smN);
    cudaFuncSetAttribute(head_kernel, cudaFuncAttributeMaxDynamicSharedMemorySize, (int)smHd);

    zero_cnt_kernel<<<(N_NODES + 255) / 256, 256>>>();
    deg_kernel<<<(N_EDGES + 255) / 256, 256>>>(dst);
    inv_kernel<<<(N_NODES + 255) / 256, 256>>>();
    lin_in_kernel<<<N_NODES, H>>>(x, lin_w, lin_b);

    for (int l = 0; l < N_LAYERS; l++) {
        zero_agg_kernel<<<1024, 256>>>();
        edge_kernel<<<sm_count, 256, smE>>>(
            src, dst, ea,
            msg_w1 + (size_t)l * KE * H, msg_b1 + (size_t)l * H,
            msg_w2 + (size_t)l * H * H, msg_b2 + (size_t)l * H);
        node_kernel<<<sm_count, 256, smN>>>(
            upd_w1 + (size_t)l * 2 * H * H, upd_b1 + (size_t)l * H,
            upd_w2 + (size_t)l * H * H, upd_b2 + (size_t)l * H);
    }

    head_kernel<<<2 * sm_count, 256, smHd>>>(head_w1, head_b1, head_w2, head_b2, out);
}

// round 5
// speedup vs baseline: 1.6948x; 1.6948x over previous
#include <cuda_runtime.h>
#include <cuda_bf16.h>
#include <cstdint>
#include <cstddef>

// ---------------------------------------------------------------------------
// MeshGNN: N=50000, E=600000, IN=16, ED=4, H=128, L=4, OUT=3
// Round 4: edge MLPs via mma.sync bf16 (HMMA) with hi/lo 3-pass split.
// (tcgen05 rejected: harness PTX target is sm_103, not sm_103a.)
// Node/head/lin_in remain scalar fp32 (round-1 proven versions).
// ---------------------------------------------------------------------------

#define N_NODES 50000
#define N_EDGES 600000
#define H 128
#define IN_F 16
#define ED 4
#define KE (H + ED)
#define N_LAYERS 4
#define N_OUT 3
#define TN 32

// padded row stride (elements) for ldmatrix tiles: 136*2B = 272B = 68 words
#define PAD 136

// smem byte offsets for edge kernel
#define SM_B1   0        // 128 f
#define SM_B2   512      // 128 f
#define SM_W1B  1024     // 512 f  (ea-part of W1: rows 128..131)
#define SM_EA   3072     // 512 f
#define SM_DST  5120     // 128 i
#define SM_AH   8192     // 128*136*2 = 34816 B
#define SM_AL   43008
#define SM_W1H  77824
#define SM_W1L  112640
#define SM_W2H  147456
#define SM_W2L  182272
#define SM_EDGE_TOTAL 217088

__device__ float g_h[(size_t)N_NODES * H];
__device__ float g_agg[(size_t)N_NODES * H];
__device__ float g_inv[N_NODES];

// ======================= helpers ==========================================

__device__ __forceinline__ uint32_t smem_u32(const void* p) {
    uint32_t a;
    asm("{ .reg .u64 t; cvta.to.shared.u64 t, %1; cvt.u32.u64 %0, t; }"
        : "=r"(a) : "l"(p));
    return a;
}

__device__ __forceinline__ void ldsm_x4(uint32_t* r, uint32_t addr) {
    asm volatile("ldmatrix.sync.aligned.m8n8.x4.shared.b16 {%0,%1,%2,%3}, [%4];"
                 : "=r"(r[0]), "=r"(r[1]), "=r"(r[2]), "=r"(r[3]) : "r"(addr));
}

__device__ __forceinline__ void mma16816(float* c, const uint32_t* a,
                                         uint32_t b0, uint32_t b1) {
    asm volatile(
        "mma.sync.aligned.m16n8k16.row.col.f32.bf16.bf16.f32 "
        "{%0,%1,%2,%3}, {%4,%5,%6,%7}, {%8,%9}, {%0,%1,%2,%3};"
        : "+f"(c[0]), "+f"(c[1]), "+f"(c[2]), "+f"(c[3])
        : "r"(a[0]), "r"(a[1]), "r"(a[2]), "r"(a[3]), "r"(b0), "r"(b1));
}

// split (x,y) into packed bf16x2 hi and lo(residual) words
__device__ __forceinline__ void hilo2(float x, float y, uint32_t& hi, uint32_t& lo) {
    __nv_bfloat16 hx = __float2bfloat16(x), hy = __float2bfloat16(y);
    __nv_bfloat162 hp = __halves2bfloat162(hx, hy);
    hi = *reinterpret_cast<uint32_t*>(&hp);
    __nv_bfloat16 lx = __float2bfloat16(x - __bfloat162float(hx));
    __nv_bfloat16 ly = __float2bfloat16(y - __bfloat162float(hy));
    __nv_bfloat162 lp = __halves2bfloat162(lx, ly);
    lo = *reinterpret_cast<uint32_t*>(&lp);
}

// ======================= small helper kernels ==============================

__global__ void zero_agg_kernel() {
    size_t i = (size_t)blockIdx.x * blockDim.x + threadIdx.x;
    const size_t n4 = (size_t)N_NODES * H / 4;
    float4 z = make_float4(0.f, 0.f, 0.f, 0.f);
    for (; i < n4; i += (size_t)gridDim.x * blockDim.x)
        reinterpret_cast<float4*>(g_agg)[i] = z;
}

__global__ void zero_cnt_kernel() {
    int i = blockIdx.x * blockDim.x + threadIdx.x;
    if (i < N_NODES) g_inv[i] = 0.f;
}

__global__ void deg_kernel(const int* __restrict__ dst) {
    int e = blockIdx.x * blockDim.x + threadIdx.x;
    if (e < N_EDGES) atomicAdd(&g_inv[dst[e]], 1.0f);
}

__global__ void inv_kernel() {
    int i = blockIdx.x * blockDim.x + threadIdx.x;
    if (i < N_NODES) g_inv[i] = 1.0f / fmaxf(g_inv[i], 1.0f);
}

__global__ void lin_in_kernel(const float* __restrict__ x,
                              const float* __restrict__ W,
                              const float* __restrict__ b) {
    __shared__ float sx[IN_F];
    int n = blockIdx.x;
    if (threadIdx.x < IN_F) sx[threadIdx.x] = x[(size_t)n * IN_F + threadIdx.x];
    __syncthreads();
    int c = threadIdx.x;
    float acc = __ldg(&b[c]);
#pragma unroll
    for (int k = 0; k < IN_F; k++)
        acc = fmaf(sx[k], __ldg(&W[k * H + c]), acc);
    g_h[(size_t)n * H + c] = fmaxf(acc, 0.f);
}

// ======================= mma edge kernel ===================================
// 256 threads = 8 warps, 1 CTA/SM, persistent. Tile = 128 edges.
// Warp w: rows m0 = 16w .. m0+15, full N=128. bf16 hi/lo, 3-pass per GEMM.

// Stage W (rows k=0..127 of [k][n] row-major fp32) transposed into smem
// WT[n][k] bf16 (hi & lo), padded row stride PAD.
__device__ __forceinline__ void stage_wt(char* smem, const float* __restrict__ W,
                                         int offH, int offL) {
    for (int idx = threadIdx.x; idx < H * H; idx += 256) {
        int k = idx >> 7, n = idx & 127;
        float v = W[idx];
        __nv_bfloat16 hb = __float2bfloat16(v);
        __nv_bfloat16 lb = __float2bfloat16(v - __bfloat162float(hb));
        int o = (n * PAD + k) * 2;
        *reinterpret_cast<__nv_bfloat16*>(smem + offH + o) = hb;
        *reinterpret_cast<__nv_bfloat16*>(smem + offL + o) = lb;
    }
}

__global__ void __launch_bounds__(256, 1)
edge_kernel(const int* __restrict__ src, const int* __restrict__ dst,
            const float* __restrict__ ea,
            const float* __restrict__ W1, const float* __restrict__ b1,
            const float* __restrict__ W2, const float* __restrict__ b2) {
    extern __shared__ char smem[];
    const uint32_t sb = smem_u32(smem);
    float* s_b1  = reinterpret_cast<float*>(smem + SM_B1);
    float* s_b2  = reinterpret_cast<float*>(smem + SM_B2);
    float* s_w1b = reinterpret_cast<float*>(smem + SM_W1B);
    float* s_ea  = reinterpret_cast<float*>(smem + SM_EA);
    int*   s_dst = reinterpret_cast<int*>(smem + SM_DST);

    const int tid  = threadIdx.x;
    const int wid  = tid >> 5;
    const int lane = tid & 31;

    stage_wt(smem, W1, SM_W1H, SM_W1L);
    stage_wt(smem, W2, SM_W2H, SM_W2L);
    if (tid < 128) {
        s_b1[tid] = b1[tid];
        s_b2[tid] = b2[tid];
#pragma unroll
        for (int j = 0; j < 4; j++) s_w1b[j * 128 + tid] = W1[(H + j) * H + tid];
    }
    __syncthreads();

    const int m0 = wid * 16;
    const int rq = lane >> 2;            // row-in-quad
    const int cp = (lane & 3) * 2;       // col pair base
    // ldmatrix lane addressing
    const uint32_t aOffLane = ((uint32_t)(m0 + (lane & 15)) * PAD + 8u * (lane >> 4)) * 2u;
    const uint32_t bOffLane = ((uint32_t)((lane & 7) + 8 * ((lane >> 3) & 1)) * PAD +
                               8u * (lane >> 4)) * 2u;

    const int NT = (N_EDGES + 127) / 128;

    for (int t = blockIdx.x; t < NT; t += gridDim.x) {
        const int e0 = t * 128;

        // ---- gather: thread handles half a row (64 channels)
        {
            const int r = tid >> 1;
            const int hc = (tid & 1) * 64;
            const int e = e0 + r;
            const bool v = (e < N_EDGES);
            const int s = v ? __ldg(&src[e]) : 0;
            const float4* hp = reinterpret_cast<const float4*>(
                g_h + (size_t)s * H + hc);
            char* dh = smem + SM_AH + (r * PAD + hc) * 2;
            char* dl = smem + SM_AL + (r * PAD + hc) * 2;
#pragma unroll
            for (int p = 0; p < 8; p++) {
                float4 v0 = v ? hp[2 * p]     : make_float4(0.f, 0.f, 0.f, 0.f);
                float4 v1 = v ? hp[2 * p + 1] : make_float4(0.f, 0.f, 0.f, 0.f);
                uint4 wh, wl;
                hilo2(v0.x, v0.y, wh.x, wl.x);
                hilo2(v0.z, v0.w, wh.y, wl.y);
                hilo2(v1.x, v1.y, wh.z, wl.z);
                hilo2(v1.z, v1.w, wh.w, wl.w);
                *reinterpret_cast<uint4*>(dh + p * 16) = wh;
                *reinterpret_cast<uint4*>(dl + p * 16) = wl;
            }
            if (tid < 128) {
                const int e2 = e0 + tid;
                const bool v2 = (e2 < N_EDGES);
                s_dst[tid] = v2 ? __ldg(&dst[e2]) : 0;
                float4 a = v2 ? *reinterpret_cast<const float4*>(ea + (size_t)e2 * ED)
                              : make_float4(0.f, 0.f, 0.f, 0.f);
                *reinterpret_cast<float4*>(s_ea + tid * 4) = a;
            }
        }
        __syncthreads();

        // ---- acc init: b1 + ea @ W1b  (rows r0 = m0+rq, r1 = r0+8)
        float acc[16][4];
        {
            float ea0[4], ea1[4];
#pragma unroll
            for (int i = 0; i < 4; i++) {
                ea0[i] = s_ea[(m0 + rq) * 4 + i];
                ea1[i] = s_ea[(m0 + rq + 8) * 4 + i];
            }
#pragma unroll
            for (int j = 0; j < 16; j++) {
                const int n = j * 8 + cp;
                float a0 = s_b1[n], a1 = s_b1[n + 1];
                float a2 = a0, a3 = a1;
#pragma unroll
                for (int i = 0; i < 4; i++) {
                    float w0 = s_w1b[i * 128 + n], w1 = s_w1b[i * 128 + n + 1];
                    a0 = fmaf(ea0[i], w0, a0);
                    a1 = fmaf(ea0[i], w1, a1);
                    a2 = fmaf(ea1[i], w0, a2);
                    a3 = fmaf(ea1[i], w1, a3);
                }
                acc[j][0] = a0; acc[j][1] = a1; acc[j][2] = a2; acc[j][3] = a3;
            }
        }

        // ---- GEMM1: 3-pass bf16 (AhBh + AlBh + AhBl)
#pragma unroll
        for (int ks = 0; ks < 8; ks++) {
            const uint32_t k0b = (uint32_t)(ks * 16) * 2u;
            uint32_t ah[4], al[4];
            ldsm_x4(ah, sb + SM_AH + aOffLane + k0b);
            ldsm_x4(al, sb + SM_AL + aOffLane + k0b);
#pragma unroll
            for (int jj = 0; jj < 8; jj++) {
                const uint32_t bo = bOffLane + k0b + (uint32_t)jj * (16 * PAD * 2);
                uint32_t bh[4], bl[4];
                ldsm_x4(bh, sb + SM_W1H + bo);
                ldsm_x4(bl, sb + SM_W1L + bo);
                mma16816(acc[2 * jj],     ah, bh[0], bh[2]);
                mma16816(acc[2 * jj + 1], ah, bh[1], bh[3]);
                mma16816(acc[2 * jj],     al, bh[0], bh[2]);
                mma16816(acc[2 * jj + 1], al, bh[1], bh[3]);
                mma16816(acc[2 * jj],     ah, bl[0], bl[2]);
                mma16816(acc[2 * jj + 1], ah, bl[1], bl[3]);
            }
        }

        // ---- relu + register re-split: C frags -> A frags for GEMM2
        uint32_t a2h[8][4], a2l[8][4];
#pragma unroll
        for (int g = 0; g < 8; g++) {
            float c0 = fmaxf(acc[2 * g][0], 0.f),     c1 = fmaxf(acc[2 * g][1], 0.f);
            float c2 = fmaxf(acc[2 * g][2], 0.f),     c3 = fmaxf(acc[2 * g][3], 0.f);
            float d0 = fmaxf(acc[2 * g + 1][0], 0.f), d1 = fmaxf(acc[2 * g + 1][1], 0.f);
            float d2 = fmaxf(acc[2 * g + 1][2], 0.f), d3 = fmaxf(acc[2 * g + 1][3], 0.f);
            hilo2(c0, c1, a2h[g][0], a2l[g][0]);
            hilo2(c2, c3, a2h[g][1], a2l[g][1]);
            hilo2(d0, d1, a2h[g][2], a2l[g][2]);
            hilo2(d2, d3, a2h[g][3], a2l[g][3]);
        }

        // ---- acc re-init with b2
#pragma unroll
        for (int j = 0; j < 16; j++) {
            const int n = j * 8 + cp;
            acc[j][0] = s_b2[n]; acc[j][1] = s_b2[n + 1];
            acc[j][2] = s_b2[n]; acc[j][3] = s_b2[n + 1];
        }

        // ---- GEMM2
#pragma unroll
        for (int ks = 0; ks < 8; ks++) {
            const uint32_t k0b = (uint32_t)(ks * 16) * 2u;
#pragma unroll
            for (int jj = 0; jj < 8; jj++) {
                const uint32_t bo = bOffLane + k0b + (uint32_t)jj * (16 * PAD * 2);
                uint32_t bh[4], bl[4];
                ldsm_x4(bh, sb + SM_W2H + bo);
                ldsm_x4(bl, sb + SM_W2L + bo);
                mma16816(acc[2 * jj],     a2h[ks], bh[0], bh[2]);
                mma16816(acc[2 * jj + 1], a2h[ks], bh[1], bh[3]);
                mma16816(acc[2 * jj],     a2l[ks], bh[0], bh[2]);
                mma16816(acc[2 * jj + 1], a2l[ks], bh[1], bh[3]);
                mma16816(acc[2 * jj],     a2h[ks], bl[0], bl[2]);
                mma16816(acc[2 * jj + 1], a2h[ks], bl[1], bl[3]);
            }
        }

        // ---- relu + float2 atomic scatter
        {
            const int r0 = m0 + rq, r1 = r0 + 8;
            const bool v0 = (e0 + r0) < N_EDGES;
            const bool v1 = (e0 + r1) < N_EDGES;
            float* p0 = g_agg + (size_t)s_dst[r0] * H;
            float* p1 = g_agg + (size_t)s_dst[r1] * H;
#pragma unroll
            for (int j = 0; j < 16; j++) {
                const int n = j * 8 + cp;
                if (v0)
                    atomicAdd(reinterpret_cast<float2*>(p0 + n),
                              make_float2(fmaxf(acc[j][0], 0.f), fmaxf(acc[j][1], 0.f)));
                if (v1)
                    atomicAdd(reinterpret_cast<float2*>(p1 + n),
                              make_float2(fmaxf(acc[j][2], 0.f), fmaxf(acc[j][3], 0.f)));
            }
        }
        __syncthreads();
    }
}

// ======================= scalar node update (round-1) ======================

__global__ void __launch_bounds__(256, 1)
node_kernel(const float* __restrict__ W1, const float* __restrict__ b1,
            const float* __restrict__ W2, const float* __restrict__ b2) {
    extern __shared__ float sm[];
    float* sW1 = sm;
    float* sW2 = sW1 + 2 * H * H;
    float* sH  = sW2 + H * H;
    float* sG  = sH + TN * H;

    for (int i = threadIdx.x; i < 2 * H * H; i += 256) sW1[i] = W1[i];
    for (int i = threadIdx.x; i < H * H; i += 256) sW2[i] = W2[i];

    const int lane = threadIdx.x & 31;
    const int w    = threadIdx.x >> 5;
    float b1v[4], b2v[4];
#pragma unroll
    for (int j = 0; j < 4; j++) {
        b1v[j] = __ldg(&b1[lane * 4 + j]);
        b2v[j] = __ldg(&b2[lane * 4 + j]);
    }
    __syncthreads();

    const int ntiles = (N_NODES + TN - 1) / TN;
    for (int t = blockIdx.x; t < ntiles; t += gridDim.x) {
        const int n0 = t * TN + w * 4;

#pragma unroll
        for (int i = 0; i < 4; i++) {
            int n = n0 + i;
            float4 hv = make_float4(0.f, 0.f, 0.f, 0.f);
            float4 gv = make_float4(0.f, 0.f, 0.f, 0.f);
            if (n < N_NODES) {
                hv = *reinterpret_cast<const float4*>(g_h + (size_t)n * H + lane * 4);
                float inv = __ldg(&g_inv[n]);
                float4 g = *reinterpret_cast<const float4*>(g_agg + (size_t)n * H + lane * 4);
                gv = make_float4(g.x * inv, g.y * inv, g.z * inv, g.w * inv);
            }
            *reinterpret_cast<float4*>(sH + (w * 4 + i) * H + lane * 4) = hv;
            *reinterpret_cast<float4*>(sG + (w * 4 + i) * H + lane * 4) = gv;
        }
        __syncwarp();

        float acc[4][4];
#pragma unroll
        for (int i = 0; i < 4; i++) {
            acc[i][0] = b1v[0]; acc[i][1] = b1v[1];
            acc[i][2] = b1v[2]; acc[i][3] = b1v[3];
        }
#pragma unroll 1
        for (int kc = 0; kc < H; kc += 4) {
            float4 a4[4];
#pragma unroll
            for (int i = 0; i < 4; i++)
                a4[i] = *reinterpret_cast<const float4*>(sH + (w * 4 + i) * H + kc);
#pragma unroll
            for (int kk = 0; kk < 4; kk++) {
                float4 bv = *reinterpret_cast<const float4*>(sW1 + (kc + kk) * H + lane * 4);
#pragma unroll
                for (int i = 0; i < 4; i++) {
                    float a = (kk == 0) ? a4[i].x : (kk == 1) ? a4[i].y
                             : (kk == 2) ? a4[i].z : a4[i].w;
                    acc[i][0] = fmaf(a, bv.x, acc[i][0]);
                    acc[i][1] = fmaf(a, bv.y, acc[i][1]);
                    acc[i][2] = fmaf(a, bv.z, acc[i][2]);
                    acc[i][3] = fmaf(a, bv.w, acc[i][3]);
                }
            }
        }
#pragma unroll 1
        for (int kc = 0; kc < H; kc += 4) {
            float4 a4[4];
#pragma unroll
            for (int i = 0; i < 4; i++)
                a4[i] = *reinterpret_cast<const float4*>(sG + (w * 4 + i) * H + kc);
#pragma unroll
            for (int kk = 0; kk < 4; kk++) {
                float4 bv = *reinterpret_cast<const float4*>(sW1 + (H + kc + kk) * H + lane * 4);
#pragma unroll
                for (int i = 0; i < 4; i++) {
                    float a = (kk == 0) ? a4[i].x : (kk == 1) ? a4[i].y
                             : (kk == 2) ? a4[i].z : a4[i].w;
                    acc[i][0] = fmaf(a, bv.x, acc[i][0]);
                    acc[i][1] = fmaf(a, bv.y, acc[i][1]);
                    acc[i][2] = fmaf(a, bv.z, acc[i][2]);
                    acc[i][3] = fmaf(a, bv.w, acc[i][3]);
                }
            }
        }
        __syncwarp();

#pragma unroll
        for (int i = 0; i < 4; i++) {
            float4 u = make_float4(fmaxf(acc[i][0], 0.f), fmaxf(acc[i][1], 0.f),
                                   fmaxf(acc[i][2], 0.f), fmaxf(acc[i][3], 0.f));
            *reinterpret_cast<float4*>(sG + (w * 4 + i) * H + lane * 4) = u;
        }
        __syncwarp();

        float acc2[4][4];
#pragma unroll
        for (int i = 0; i < 4; i++) {
            acc2[i][0] = b2v[0]; acc2[i][1] = b2v[1];
            acc2[i][2] = b2v[2]; acc2[i][3] = b2v[3];
        }
#pragma unroll 1
        for (int kc = 0; kc < H; kc += 4) {
            float4 a4[4];
#pragma unroll
            for (int i = 0; i < 4; i++)
                a4[i] = *reinterpret_cast<const float4*>(sG + (w * 4 + i) * H + kc);
#pragma unroll
            for (int kk = 0; kk < 4; kk++) {
                float4 bv = *reinterpret_cast<const float4*>(sW2 + (kc + kk) * H + lane * 4);
#pragma unroll
                for (int i = 0; i < 4; i++) {
                    float a = (kk == 0) ? a4[i].x : (kk == 1) ? a4[i].y
                             : (kk == 2) ? a4[i].z : a4[i].w;
                    acc2[i][0] = fmaf(a, bv.x, acc2[i][0]);
                    acc2[i][1] = fmaf(a, bv.y, acc2[i][1]);
                    acc2[i][2] = fmaf(a, bv.z, acc2[i][2]);
                    acc2[i][3] = fmaf(a, bv.w, acc2[i][3]);
                }
            }
        }
#pragma unroll
        for (int i = 0; i < 4; i++) {
            int n = n0 + i;
            if (n < N_NODES) {
                float4 hv = *reinterpret_cast<const float4*>(sH + (w * 4 + i) * H + lane * 4);
                float4 o = make_float4(fmaxf(acc2[i][0] + hv.x, 0.f),
                                       fmaxf(acc2[i][1] + hv.y, 0.f),
                                       fmaxf(acc2[i][2] + hv.z, 0.f),
                                       fmaxf(acc2[i][3] + hv.w, 0.f));
                *reinterpret_cast<float4*>(g_h + (size_t)n * H + lane * 4) = o;
            }
        }
        __syncwarp();
    }
}

// ======================= head (round-1) ====================================

__global__ void __launch_bounds__(256, 1)
head_kernel(const float* __restrict__ W1, const float* __restrict__ b1,
            const float* __restrict__ W2, const float* __restrict__ b2,
            float* __restrict__ out) {
    extern __shared__ float sm[];
    float* sW1 = sm;
    float* sW2 = sW1 + H * H;
    float* sH  = sW2 + H * N_OUT;

    for (int i = threadIdx.x; i < H * H; i += 256) sW1[i] = W1[i];
    for (int i = threadIdx.x; i < H * N_OUT; i += 256) sW2[i] = W2[i];

    const int lane = threadIdx.x & 31;
    const int w    = threadIdx.x >> 5;
    float b1v[4];
#pragma unroll
    for (int j = 0; j < 4; j++) b1v[j] = __ldg(&b1[lane * 4 + j]);
    const float b2v0 = __ldg(&b2[0]), b2v1 = __ldg(&b2[1]), b2v2 = __ldg(&b2[2]);
    __syncthreads();

    const int ntiles = (N_NODES + TN - 1) / TN;
    for (int t = blockIdx.x; t < ntiles; t += gridDim.x) {
        const int n0 = t * TN + w * 4;
#pragma unroll
        for (int i = 0; i < 4; i++) {
            int n = n0 + i;
            float4 hv = make_float4(0.f, 0.f, 0.f, 0.f);
            if (n < N_NODES)
                hv = *reinterpret_cast<const float4*>(g_h + (size_t)n * H + lane * 4);
            *reinterpret_cast<float4*>(sH + (w * 4 + i) * H + lane * 4) = hv;
        }
        __syncwarp();

        float acc[4][4];
#pragma unroll
        for (int i = 0; i < 4; i++) {
            acc[i][0] = b1v[0]; acc[i][1] = b1v[1];
            acc[i][2] = b1v[2]; acc[i][3] = b1v[3];
        }
#pragma unroll 1
        for (int kc = 0; kc < H; kc += 4) {
            float4 a4[4];
#pragma unroll
            for (int i = 0; i < 4; i++)
                a4[i] = *reinterpret_cast<const float4*>(sH + (w * 4 + i) * H + kc);
#pragma unroll
            for (int kk = 0; kk < 4; kk++) {
                float4 bv = *reinterpret_cast<const float4*>(sW1 + (kc + kk) * H + lane * 4);
#pragma unroll
                for (int i = 0; i < 4; i++) {
                    float a = (kk == 0) ? a4[i].x : (kk == 1) ? a4[i].y
                             : (kk == 2) ? a4[i].z : a4[i].w;
                    acc[i][0] = fmaf(a, bv.x, acc[i][0]);
                    acc[i][1] = fmaf(a, bv.y, acc[i][1]);
                    acc[i][2] = fmaf(a, bv.z, acc[i][2]);
                    acc[i][3] = fmaf(a, bv.w, acc[i][3]);
                }
            }
        }

#pragma unroll
        for (int i = 0; i < 4; i++) {
            float p0 = 0.f, p1 = 0.f, p2 = 0.f;
#pragma unroll
            for (int j = 0; j < 4; j++) {
                float o = fmaxf(acc[i][j], 0.f);
                int kk = lane * 4 + j;
                p0 = fmaf(o, sW2[kk * N_OUT + 0], p0);
                p1 = fmaf(o, sW2[kk * N_OUT + 1], p1);
                p2 = fmaf(o, sW2[kk * N_OUT + 2], p2);
            }
#pragma unroll
            for (int off = 16; off > 0; off >>= 1) {
                p0 += __shfl_xor_sync(0xffffffffu, p0, off);
                p1 += __shfl_xor_sync(0xffffffffu, p1, off);
                p2 += __shfl_xor_sync(0xffffffffu, p2, off);
            }
            int n = n0 + i;
            if (lane == 0 && n < N_NODES) {
                out[(size_t)n * N_OUT + 0] = fmaxf(p0 + b2v0, 0.f);
                out[(size_t)n * N_OUT + 1] = fmaxf(p1 + b2v1, 0.f);
                out[(size_t)n * N_OUT + 2] = fmaxf(p2 + b2v2, 0.f);
            }
        }
        __syncwarp();
    }
}

// ======================= launch ============================================

extern "C" void kernel_launch(void* const* d_in, const int* in_sizes, int n_in,
                              void* d_out, int out_size) {
    const float* x       = (const float*)d_in[0];
    const int*   ei      = (const int*)d_in[1];
    const float* ea      = (const float*)d_in[2];
    const float* lin_w   = (const float*)d_in[3];
    const float* lin_b   = (const float*)d_in[4];
    const float* msg_w1  = (const float*)d_in[5];
    const float* msg_b1  = (const float*)d_in[6];
    const float* msg_w2  = (const float*)d_in[7];
    const float* msg_b2  = (const float*)d_in[8];
    const float* upd_w1  = (const float*)d_in[9];
    const float* upd_b1  = (const float*)d_in[10];
    const float* upd_w2  = (const float*)d_in[11];
    const float* upd_b2  = (const float*)d_in[12];
    const float* head_w1 = (const float*)d_in[13];
    const float* head_b1 = (const float*)d_in[14];
    const float* head_w2 = (const float*)d_in[15];
    const float* head_b2 = (const float*)d_in[16];
    float* out = (float*)d_out;

    const int* src = ei;
    const int* dst = ei + N_EDGES;

    int sm_count = 148;
    cudaDeviceGetAttribute(&sm_count, cudaDevAttrMultiProcessorCount, 0);

    const size_t smN  = (size_t)(2 * H * H + H * H + 2 * TN * H) * sizeof(float);
    const size_t smHd = (size_t)(H * H + H * N_OUT + TN * H) * sizeof(float);
    cudaFuncSetAttribute(edge_kernel, cudaFuncAttributeMaxDynamicSharedMemorySize, SM_EDGE_TOTAL);
    cudaFuncSetAttribute(node_kernel, cudaFuncAttributeMaxDynamicSharedMemorySize, (int)smN);
    cudaFuncSetAttribute(head_kernel, cudaFuncAttributeMaxDynamicSharedMemorySize, (int)smHd);

    zero_cnt_kernel<<<(N_NODES + 255) / 256, 256>>>();
    deg_kernel<<<(N_EDGES + 255) / 256, 256>>>(dst);
    inv_kernel<<<(N_NODES + 255) / 256, 256>>>();
    lin_in_kernel<<<N_NODES, H>>>(x, lin_w, lin_b);

    for (int l = 0; l < N_LAYERS; l++) {
        zero_agg_kernel<<<1024, 256>>>();
        edge_kernel<<<sm_count, 256, SM_EDGE_TOTAL>>>(
            src, dst, ea,
            msg_w1 + (size_t)l * KE * H, msg_b1 + (size_t)l * H,
            msg_w2 + (size_t)l * H * H, msg_b2 + (size_t)l * H);
        node_kernel<<<sm_count, 256, smN>>>(
            upd_w1 + (size_t)l * 2 * H * H, upd_b1 + (size_t)l * H,
            upd_w2 + (size_t)l * H * H, upd_b2 + (size_t)l * H);
    }

    head_kernel<<<2 * sm_count, 256, smHd>>>(head_w1, head_b1, head_w2, head_b2, out);
}

// round 6
// speedup vs baseline: 1.9654x; 1.1597x over previous
#include <cuda_runtime.h>
#include <cuda_bf16.h>
#include <cstdint>
#include <cstddef>

// ---------------------------------------------------------------------------
// MeshGNN: N=50000, E=600000, IN=16, ED=4, H=128, L=4, OUT=3
// Round 5: (1) edge kernel dual-group (2x4 warps) pipelining with named
// barriers, 64-edge tiles (no remainder); (2) node update on HMMA 3-pass,
// split into node1 (K=256, writes packed bf16 U) + node2 (K=128 + residual).
// ---------------------------------------------------------------------------

#define N_NODES 50000
#define N_EDGES 600000
#define H 128
#define IN_F 16
#define ED 4
#define N_LAYERS 4
#define N_OUT 3
#define TN 32

#define PAD  136   // k stride (elements) for K=128 ldmatrix tiles
#define PADW 264   // k stride (elements) for K=256 W1 tile

// ---- edge kernel smem map (bytes)
#define SM_B1   0
#define SM_B2   512
#define SM_W1B  1024
#define SM_EA   3072     // +g*1024
#define SM_DST  5120     // +g*256
#define SM_W1H  8192
#define SM_W1L  43008
#define SM_W2H  77824
#define SM_W2L  112640
#define SM_AH   147456   // +g*17408
#define SM_AL   182272   // +g*17408
#define SM_EDGE_TOTAL 217088

// ---- node1 smem map
#define N1_B1   0
#define N1_W1H  1024
#define N1_W1L  68608
#define N1_AH   136192
#define N1_AL   171008
#define N1_TOTAL 205824

// ---- node2 smem map
#define N2_B2   0
#define N2_W2H  1024
#define N2_W2L  35840
#define N2_AH   70656
#define N2_AL   105472
#define N2_TOTAL 140288

__device__ float g_h[(size_t)N_NODES * H];
__device__ float g_agg[(size_t)N_NODES * H];
__device__ float g_inv[N_NODES];
__device__ uint32_t g_u[(size_t)N_NODES * 128];  // packed bf16 U: hi[64] lo[64] per node

// ======================= helpers ==========================================

__device__ __forceinline__ uint32_t smem_u32(const void* p) {
    uint32_t a;
    asm("{ .reg .u64 t; cvta.to.shared.u64 t, %1; cvt.u32.u64 %0, t; }"
        : "=r"(a) : "l"(p));
    return a;
}

__device__ __forceinline__ void ldsm_x4(uint32_t* r, uint32_t addr) {
    asm volatile("ldmatrix.sync.aligned.m8n8.x4.shared.b16 {%0,%1,%2,%3}, [%4];"
                 : "=r"(r[0]), "=r"(r[1]), "=r"(r[2]), "=r"(r[3]) : "r"(addr));
}

__device__ __forceinline__ void mma16816(float* c, const uint32_t* a,
                                         uint32_t b0, uint32_t b1) {
    asm volatile(
        "mma.sync.aligned.m16n8k16.row.col.f32.bf16.bf16.f32 "
        "{%0,%1,%2,%3}, {%4,%5,%6,%7}, {%8,%9}, {%0,%1,%2,%3};"
        : "+f"(c[0]), "+f"(c[1]), "+f"(c[2]), "+f"(c[3])
        : "r"(a[0]), "r"(a[1]), "r"(a[2]), "r"(a[3]), "r"(b0), "r"(b1));
}

__device__ __forceinline__ void hilo2(float x, float y, uint32_t& hi, uint32_t& lo) {
    __nv_bfloat16 hx = __float2bfloat16(x), hy = __float2bfloat16(y);
    __nv_bfloat162 hp = __halves2bfloat162(hx, hy);
    hi = *reinterpret_cast<uint32_t*>(&hp);
    __nv_bfloat16 lx = __float2bfloat16(x - __bfloat162float(hx));
    __nv_bfloat16 ly = __float2bfloat16(y - __bfloat162float(hy));
    __nv_bfloat162 lp = __halves2bfloat162(lx, ly);
    lo = *reinterpret_cast<uint32_t*>(&lp);
}

#define GROUP_BAR(gid) \
    asm volatile("bar.sync %0, %1;" :: "r"(1 + (gid)), "r"(128) : "memory")

// ======================= small helper kernels ==============================

__global__ void zero_agg_kernel() {
    size_t i = (size_t)blockIdx.x * blockDim.x + threadIdx.x;
    const size_t n4 = (size_t)N_NODES * H / 4;
    float4 z = make_float4(0.f, 0.f, 0.f, 0.f);
    for (; i < n4; i += (size_t)gridDim.x * blockDim.x)
        reinterpret_cast<float4*>(g_agg)[i] = z;
}

__global__ void zero_cnt_kernel() {
    int i = blockIdx.x * blockDim.x + threadIdx.x;
    if (i < N_NODES) g_inv[i] = 0.f;
}

__global__ void deg_kernel(const int* __restrict__ dst) {
    int e = blockIdx.x * blockDim.x + threadIdx.x;
    if (e < N_EDGES) atomicAdd(&g_inv[dst[e]], 1.0f);
}

__global__ void inv_kernel() {
    int i = blockIdx.x * blockDim.x + threadIdx.x;
    if (i < N_NODES) g_inv[i] = 1.0f / fmaxf(g_inv[i], 1.0f);
}

__global__ void lin_in_kernel(const float* __restrict__ x,
                              const float* __restrict__ W,
                              const float* __restrict__ b) {
    __shared__ float sx[IN_F];
    int n = blockIdx.x;
    if (threadIdx.x < IN_F) sx[threadIdx.x] = x[(size_t)n * IN_F + threadIdx.x];
    __syncthreads();
    int c = threadIdx.x;
    float acc = __ldg(&b[c]);
#pragma unroll
    for (int k = 0; k < IN_F; k++)
        acc = fmaf(sx[k], __ldg(&W[k * H + c]), acc);
    g_h[(size_t)n * H + c] = fmaxf(acc, 0.f);
}

// stage W[k][n] fp32 (k rows, 128 cols) transposed into WT[n][k] bf16 hi/lo,
// row stride `pad` elements, k range [0, kdim)
__device__ __forceinline__ void stage_wt(char* smem, const float* __restrict__ W,
                                         int offH, int offL, int kdim, int pad) {
    for (int idx = threadIdx.x; idx < kdim * H; idx += blockDim.x) {
        int k = idx >> 7, n = idx & 127;
        float v = W[idx];
        __nv_bfloat16 hb = __float2bfloat16(v);
        __nv_bfloat16 lb = __float2bfloat16(v - __bfloat162float(hb));
        int o = (n * pad + k) * 2;
        *reinterpret_cast<__nv_bfloat16*>(smem + offH + o) = hb;
        *reinterpret_cast<__nv_bfloat16*>(smem + offL + o) = lb;
    }
}

// ======================= edge kernel (dual-group pipelined) ================
// 256 thr = 8 warps = 2 groups x 4 warps. Tile = 64 edges per group.
// Warp (group g, local lw) owns rows m0 = lw*16 .. +15 of its group's tile.

__global__ void __launch_bounds__(256, 1)
edge_kernel(const int* __restrict__ src, const int* __restrict__ dst,
            const float* __restrict__ ea,
            const float* __restrict__ W1, const float* __restrict__ b1,
            const float* __restrict__ W2, const float* __restrict__ b2) {
    extern __shared__ char smem[];
    const uint32_t sb = smem_u32(smem);
    float* s_b1  = reinterpret_cast<float*>(smem + SM_B1);
    float* s_b2  = reinterpret_cast<float*>(smem + SM_B2);
    float* s_w1b = reinterpret_cast<float*>(smem + SM_W1B);

    const int tid  = threadIdx.x;
    const int wid  = tid >> 5;
    const int lane = tid & 31;
    const int g    = wid >> 2;       // group 0/1
    const int lw   = wid & 3;        // warp in group
    const int ltid = tid & 127;      // thread in group

    stage_wt(smem, W1, SM_W1H, SM_W1L, H, PAD);
    stage_wt(smem, W2, SM_W2H, SM_W2L, H, PAD);
    if (tid < 128) {
        s_b1[tid] = b1[tid];
        s_b2[tid] = b2[tid];
#pragma unroll
        for (int j = 0; j < 4; j++) s_w1b[j * 128 + tid] = W1[(H + j) * H + tid];
    }
    __syncthreads();

    float* s_ea  = reinterpret_cast<float*>(smem + SM_EA + g * 1024);
    int*   s_dst = reinterpret_cast<int*>(smem + SM_DST + g * 256);
    char*  sAH   = smem + SM_AH + g * 17408;
    char*  sAL   = smem + SM_AL + g * 17408;
    const uint32_t bAH = sb + SM_AH + g * 17408;
    const uint32_t bAL = sb + SM_AL + g * 17408;

    const int m0 = lw * 16;
    const int rq = lane >> 2;
    const int cp = (lane & 3) * 2;
    const uint32_t aOffLane = ((uint32_t)(m0 + (lane & 15)) * PAD + 8u * (lane >> 4)) * 2u;
    const uint32_t bOffLane = ((uint32_t)((lane & 7) + 8 * ((lane >> 3) & 1)) * PAD +
                               8u * (lane >> 4)) * 2u;

    const int NT = N_EDGES / 64;  // 9375 exactly

    for (int t = blockIdx.x * 2 + g; t < NT; t += gridDim.x * 2) {
        const int e0 = t * 64;

        // ---- gather: 128 group threads, each half a row (64 channels)
        {
            const int r = ltid >> 1;
            const int hc = (ltid & 1) * 64;
            const int s = __ldg(&src[e0 + r]);
            const float4* hp = reinterpret_cast<const float4*>(g_h + (size_t)s * H + hc);
            char* dh = sAH + (r * PAD + hc) * 2;
            char* dl = sAL + (r * PAD + hc) * 2;
#pragma unroll
            for (int p = 0; p < 8; p++) {
                float4 v0 = hp[2 * p];
                float4 v1 = hp[2 * p + 1];
                uint4 wh, wl;
                hilo2(v0.x, v0.y, wh.x, wl.x);
                hilo2(v0.z, v0.w, wh.y, wl.y);
                hilo2(v1.x, v1.y, wh.z, wl.z);
                hilo2(v1.z, v1.w, wh.w, wl.w);
                *reinterpret_cast<uint4*>(dh + p * 16) = wh;
                *reinterpret_cast<uint4*>(dl + p * 16) = wl;
            }
            if (ltid < 64) {
                s_dst[ltid] = __ldg(&dst[e0 + ltid]);
                float4 a = *reinterpret_cast<const float4*>(ea + (size_t)(e0 + ltid) * ED);
                *reinterpret_cast<float4*>(s_ea + ltid * 4) = a;
            }
        }
        GROUP_BAR(g);

        // ---- acc init: b1 + ea @ W1b
        float acc[16][4];
        {
            float ea0[4], ea1[4];
#pragma unroll
            for (int i = 0; i < 4; i++) {
                ea0[i] = s_ea[(m0 + rq) * 4 + i];
                ea1[i] = s_ea[(m0 + rq + 8) * 4 + i];
            }
#pragma unroll
            for (int j = 0; j < 16; j++) {
                const int n = j * 8 + cp;
                float a0 = s_b1[n], a1 = s_b1[n + 1];
                float a2 = a0, a3 = a1;
#pragma unroll
                for (int i = 0; i < 4; i++) {
                    float w0 = s_w1b[i * 128 + n], w1 = s_w1b[i * 128 + n + 1];
                    a0 = fmaf(ea0[i], w0, a0);
                    a1 = fmaf(ea0[i], w1, a1);
                    a2 = fmaf(ea1[i], w0, a2);
                    a3 = fmaf(ea1[i], w1, a3);
                }
                acc[j][0] = a0; acc[j][1] = a1; acc[j][2] = a2; acc[j][3] = a3;
            }
        }

        // ---- GEMM1 (3-pass)
#pragma unroll
        for (int ks = 0; ks < 8; ks++) {
            const uint32_t k0b = (uint32_t)(ks * 16) * 2u;
            uint32_t ah[4], al[4];
            ldsm_x4(ah, bAH + aOffLane + k0b);
            ldsm_x4(al, bAL + aOffLane + k0b);
#pragma unroll
            for (int jj = 0; jj < 8; jj++) {
                const uint32_t bo = bOffLane + k0b + (uint32_t)jj * (16 * PAD * 2);
                uint32_t bh[4], bl[4];
                ldsm_x4(bh, sb + SM_W1H + bo);
                ldsm_x4(bl, sb + SM_W1L + bo);
                mma16816(acc[2 * jj],     ah, bh[0], bh[2]);
                mma16816(acc[2 * jj + 1], ah, bh[1], bh[3]);
                mma16816(acc[2 * jj],     al, bh[0], bh[2]);
                mma16816(acc[2 * jj + 1], al, bh[1], bh[3]);
                mma16816(acc[2 * jj],     ah, bl[0], bl[2]);
                mma16816(acc[2 * jj + 1], ah, bl[1], bl[3]);
            }
        }

        // ---- relu + register re-split
        uint32_t a2h[8][4], a2l[8][4];
#pragma unroll
        for (int gg = 0; gg < 8; gg++) {
            float c0 = fmaxf(acc[2 * gg][0], 0.f),     c1 = fmaxf(acc[2 * gg][1], 0.f);
            float c2 = fmaxf(acc[2 * gg][2], 0.f),     c3 = fmaxf(acc[2 * gg][3], 0.f);
            float d0 = fmaxf(acc[2 * gg + 1][0], 0.f), d1 = fmaxf(acc[2 * gg + 1][1], 0.f);
            float d2 = fmaxf(acc[2 * gg + 1][2], 0.f), d3 = fmaxf(acc[2 * gg + 1][3], 0.f);
            hilo2(c0, c1, a2h[gg][0], a2l[gg][0]);
            hilo2(c2, c3, a2h[gg][1], a2l[gg][1]);
            hilo2(d0, d1, a2h[gg][2], a2l[gg][2]);
            hilo2(d2, d3, a2h[gg][3], a2l[gg][3]);
        }

#pragma unroll
        for (int j = 0; j < 16; j++) {
            const int n = j * 8 + cp;
            acc[j][0] = s_b2[n]; acc[j][1] = s_b2[n + 1];
            acc[j][2] = s_b2[n]; acc[j][3] = s_b2[n + 1];
        }

        // ---- GEMM2 (3-pass)
#pragma unroll
        for (int ks = 0; ks < 8; ks++) {
            const uint32_t k0b = (uint32_t)(ks * 16) * 2u;
#pragma unroll
            for (int jj = 0; jj < 8; jj++) {
                const uint32_t bo = bOffLane + k0b + (uint32_t)jj * (16 * PAD * 2);
                uint32_t bh[4], bl[4];
                ldsm_x4(bh, sb + SM_W2H + bo);
                ldsm_x4(bl, sb + SM_W2L + bo);
                mma16816(acc[2 * jj],     a2h[ks], bh[0], bh[2]);
                mma16816(acc[2 * jj + 1], a2h[ks], bh[1], bh[3]);
                mma16816(acc[2 * jj],     a2l[ks], bh[0], bh[2]);
                mma16816(acc[2 * jj + 1], a2l[ks], bh[1], bh[3]);
                mma16816(acc[2 * jj],     a2h[ks], bl[0], bl[2]);
                mma16816(acc[2 * jj + 1], a2h[ks], bl[1], bl[3]);
            }
        }

        // ---- relu + float2 atomic scatter
        {
            const int r0 = m0 + rq, r1 = r0 + 8;
            float* p0 = g_agg + (size_t)s_dst[r0] * H;
            float* p1 = g_agg + (size_t)s_dst[r1] * H;
#pragma unroll
            for (int j = 0; j < 16; j++) {
                const int n = j * 8 + cp;
                atomicAdd(reinterpret_cast<float2*>(p0 + n),
                          make_float2(fmaxf(acc[j][0], 0.f), fmaxf(acc[j][1], 0.f)));
                atomicAdd(reinterpret_cast<float2*>(p1 + n),
                          make_float2(fmaxf(acc[j][2], 0.f), fmaxf(acc[j][3], 0.f)));
            }
        }
        GROUP_BAR(g);  // A tile fully consumed before next gather overwrites
    }
}

// ======================= node1: U = relu([h|agg/cnt]@W1 + b1) ==============
// 256 thr = 8 warps, tile = 128 nodes, K=256 done as two K=128 phases.
// Output U written as packed bf16 hi/lo planes to g_u.

__global__ void __launch_bounds__(256, 1)
node1_kernel(const float* __restrict__ W1, const float* __restrict__ b1) {
    extern __shared__ char smem[];
    const uint32_t sb = smem_u32(smem);
    float* s_b1 = reinterpret_cast<float*>(smem + N1_B1);

    const int tid  = threadIdx.x;
    const int wid  = tid >> 5;
    const int lane = tid & 31;

    stage_wt(smem, W1, N1_W1H, N1_W1L, 2 * H, PADW);
    if (tid < 128) s_b1[tid] = b1[tid];
    __syncthreads();

    const int m0 = wid * 16;
    const int rq = lane >> 2;
    const int cp = (lane & 3) * 2;
    const uint32_t aOffLane = ((uint32_t)(m0 + (lane & 15)) * PAD + 8u * (lane >> 4)) * 2u;
    const uint32_t bOffLane = ((uint32_t)((lane & 7) + 8 * ((lane >> 3) & 1)) * PADW +
                               8u * (lane >> 4)) * 2u;

    const int NTN = (N_NODES + 127) / 128;  // 391

    for (int t = blockIdx.x; t < NTN; t += gridDim.x) {
        float acc[16][4];
#pragma unroll
        for (int j = 0; j < 16; j++) {
            const int n = j * 8 + cp;
            acc[j][0] = s_b1[n]; acc[j][1] = s_b1[n + 1];
            acc[j][2] = s_b1[n]; acc[j][3] = s_b1[n + 1];
        }

#pragma unroll 1
        for (int phase = 0; phase < 2; phase++) {
            // stage A: phase 0 = h rows, phase 1 = agg*inv rows
            {
                const int r = tid >> 1;
                const int hc = (tid & 1) * 64;
                const int node = t * 128 + r;
                const bool v = (node < N_NODES);
                const float* base = (phase == 0) ? g_h : g_agg;
                const float* hp = base + (size_t)(v ? node : 0) * H + hc;
                const float sc = (phase == 1 && v) ? __ldg(&g_inv[node]) : 1.0f;
                char* dh = smem + N1_AH + (r * PAD + hc) * 2;
                char* dl = smem + N1_AL + (r * PAD + hc) * 2;
#pragma unroll
                for (int p = 0; p < 8; p++) {
                    float4 v0 = v ? *reinterpret_cast<const float4*>(hp + 8 * p)
                                  : make_float4(0.f, 0.f, 0.f, 0.f);
                    float4 v1 = v ? *reinterpret_cast<const float4*>(hp + 8 * p + 4)
                                  : make_float4(0.f, 0.f, 0.f, 0.f);
                    uint4 wh, wl;
                    hilo2(v0.x * sc, v0.y * sc, wh.x, wl.x);
                    hilo2(v0.z * sc, v0.w * sc, wh.y, wl.y);
                    hilo2(v1.x * sc, v1.y * sc, wh.z, wl.z);
                    hilo2(v1.z * sc, v1.w * sc, wh.w, wl.w);
                    *reinterpret_cast<uint4*>(dh + p * 16) = wh;
                    *reinterpret_cast<uint4*>(dl + p * 16) = wl;
                }
            }
            __syncthreads();

            const uint32_t kbase = (uint32_t)(phase * 128) * 2u;
#pragma unroll
            for (int ks = 0; ks < 8; ks++) {
                const uint32_t k0a = (uint32_t)(ks * 16) * 2u;
                const uint32_t k0b = kbase + k0a;
                uint32_t ah[4], al[4];
                ldsm_x4(ah, sb + N1_AH + aOffLane + k0a);
                ldsm_x4(al, sb + N1_AL + aOffLane + k0a);
#pragma unroll
                for (int jj = 0; jj < 8; jj++) {
                    const uint32_t bo = bOffLane + k0b + (uint32_t)jj * (16 * PADW * 2);
                    uint32_t bh[4], bl[4];
                    ldsm_x4(bh, sb + N1_W1H + bo);
                    ldsm_x4(bl, sb + N1_W1L + bo);
                    mma16816(acc[2 * jj],     ah, bh[0], bh[2]);
                    mma16816(acc[2 * jj + 1], ah, bh[1], bh[3]);
                    mma16816(acc[2 * jj],     al, bh[0], bh[2]);
                    mma16816(acc[2 * jj + 1], al, bh[1], bh[3]);
                    mma16816(acc[2 * jj],     ah, bl[0], bl[2]);
                    mma16816(acc[2 * jj + 1], ah, bl[1], bl[3]);
                }
            }
            __syncthreads();  // A consumed before next phase/tile restages
        }

        // epilogue: relu -> packed hi/lo -> g_u
        {
            const int r0 = m0 + rq, r1 = r0 + 8;
            const int n0 = t * 128 + r0, n1 = t * 128 + r1;
            const int wq = lane & 3;
#pragma unroll
            for (int j = 0; j < 16; j++) {
                const int w = j * 4 + wq;
                uint32_t hi0, lo0, hi1, lo1;
                hilo2(fmaxf(acc[j][0], 0.f), fmaxf(acc[j][1], 0.f), hi0, lo0);
                hilo2(fmaxf(acc[j][2], 0.f), fmaxf(acc[j][3], 0.f), hi1, lo1);
                if (n0 < N_NODES) {
                    g_u[(size_t)n0 * 128 + w]      = hi0;
                    g_u[(size_t)n0 * 128 + 64 + w] = lo0;
                }
                if (n1 < N_NODES) {
                    g_u[(size_t)n1 * 128 + w]      = hi1;
                    g_u[(size_t)n1 * 128 + 64 + w] = lo1;
                }
            }
        }
    }
}

// ======================= node2: h = relu(U@W2 + b2 + h) ====================

__global__ void __launch_bounds__(256, 1)
node2_kernel(const float* __restrict__ W2, const float* __restrict__ b2) {
    extern __shared__ char smem[];
    const uint32_t sb = smem_u32(smem);
    float* s_b2 = reinterpret_cast<float*>(smem + N2_B2);

    const int tid  = threadIdx.x;
    const int wid  = tid >> 5;
    const int lane = tid & 31;

    stage_wt(smem, W2, N2_W2H, N2_W2L, H, PAD);
    if (tid < 128) s_b2[tid] = b2[tid];
    __syncthreads();

    const int m0 = wid * 16;
    const int rq = lane >> 2;
    const int cp = (lane & 3) * 2;
    const uint32_t aOffLane = ((uint32_t)(m0 + (lane & 15)) * PAD + 8u * (lane >> 4)) * 2u;
    const uint32_t bOffLane = ((uint32_t)((lane & 7) + 8 * ((lane >> 3) & 1)) * PAD +
                               8u * (lane >> 4)) * 2u;

    const int NTN = (N_NODES + 127) / 128;

    for (int t = blockIdx.x; t < NTN; t += gridDim.x) {
        // stage A (already packed bf16 hi/lo in g_u)
        for (int i = tid; i < 128 * 64; i += 256) {
            const int r = i >> 6, w = i & 63;
            const int node = t * 128 + r;
            uint32_t hi = 0, lo = 0;
            if (node < N_NODES) {
                hi = g_u[(size_t)node * 128 + w];
                lo = g_u[(size_t)node * 128 + 64 + w];
            }
            const int o = (r * PAD + 2 * w) * 2;
            *reinterpret_cast<uint32_t*>(smem + N2_AH + o) = hi;
            *reinterpret_cast<uint32_t*>(smem + N2_AL + o) = lo;
        }
        __syncthreads();

        float acc[16][4];
#pragma unroll
        for (int j = 0; j < 16; j++) {
            const int n = j * 8 + cp;
            acc[j][0] = s_b2[n]; acc[j][1] = s_b2[n + 1];
            acc[j][2] = s_b2[n]; acc[j][3] = s_b2[n + 1];
        }

#pragma unroll
        for (int ks = 0; ks < 8; ks++) {
            const uint32_t k0b = (uint32_t)(ks * 16) * 2u;
            uint32_t ah[4], al[4];
            ldsm_x4(ah, sb + N2_AH + aOffLane + k0b);
            ldsm_x4(al, sb + N2_AL + aOffLane + k0b);
#pragma unroll
            for (int jj = 0; jj < 8; jj++) {
                const uint32_t bo = bOffLane + k0b + (uint32_t)jj * (16 * PAD * 2);
                uint32_t bh[4], bl[4];
                ldsm_x4(bh, sb + N2_W2H + bo);
                ldsm_x4(bl, sb + N2_W2L + bo);
                mma16816(acc[2 * jj],     ah, bh[0], bh[2]);
                mma16816(acc[2 * jj + 1], ah, bh[1], bh[3]);
                mma16816(acc[2 * jj],     al, bh[0], bh[2]);
                mma16816(acc[2 * jj + 1], al, bh[1], bh[3]);
                mma16816(acc[2 * jj],     ah, bl[0], bl[2]);
                mma16816(acc[2 * jj + 1], ah, bl[1], bl[3]);
            }
        }

        // epilogue: + h residual, relu, write back
        {
            const int r0 = m0 + rq, r1 = r0 + 8;
            const int n0 = t * 128 + r0, n1 = t * 128 + r1;
#pragma unroll
            for (int j = 0; j < 16; j++) {
                const int n = j * 8 + cp;
                if (n0 < N_NODES) {
                    float2 h0 = *reinterpret_cast<const float2*>(g_h + (size_t)n0 * H + n);
                    float2 o0 = make_float2(fmaxf(acc[j][0] + h0.x, 0.f),
                                            fmaxf(acc[j][1] + h0.y, 0.f));
                    *reinterpret_cast<float2*>(g_h + (size_t)n0 * H + n) = o0;
                }
                if (n1 < N_NODES) {
                    float2 h1 = *reinterpret_cast<const float2*>(g_h + (size_t)n1 * H + n);
                    float2 o1 = make_float2(fmaxf(acc[j][2] + h1.x, 0.f),
                                            fmaxf(acc[j][3] + h1.y, 0.f));
                    *reinterpret_cast<float2*>(g_h + (size_t)n1 * H + n) = o1;
                }
            }
        }
        __syncthreads();
    }
}

// ======================= head (round-1) ====================================

__global__ void __launch_bounds__(256, 1)
head_kernel(const float* __restrict__ W1, const float* __restrict__ b1,
            const float* __restrict__ W2, const float* __restrict__ b2,
            float* __restrict__ out) {
    extern __shared__ float sm[];
    float* sW1 = sm;
    float* sW2 = sW1 + H * H;
    float* sH  = sW2 + H * N_OUT;

    for (int i = threadIdx.x; i < H * H; i += 256) sW1[i] = W1[i];
    for (int i = threadIdx.x; i < H * N_OUT; i += 256) sW2[i] = W2[i];

    const int lane = threadIdx.x & 31;
    const int w    = threadIdx.x >> 5;
    float b1v[4];
#pragma unroll
    for (int j = 0; j < 4; j++) b1v[j] = __ldg(&b1[lane * 4 + j]);
    const float b2v0 = __ldg(&b2[0]), b2v1 = __ldg(&b2[1]), b2v2 = __ldg(&b2[2]);
    __syncthreads();

    const int ntiles = (N_NODES + TN - 1) / TN;
    for (int t = blockIdx.x; t < ntiles; t += gridDim.x) {
        const int n0 = t * TN + w * 4;
#pragma unroll
        for (int i = 0; i < 4; i++) {
            int n = n0 + i;
            float4 hv = make_float4(0.f, 0.f, 0.f, 0.f);
            if (n < N_NODES)
                hv = *reinterpret_cast<const float4*>(g_h + (size_t)n * H + lane * 4);
            *reinterpret_cast<float4*>(sH + (w * 4 + i) * H + lane * 4) = hv;
        }
        __syncwarp();

        float acc[4][4];
#pragma unroll
        for (int i = 0; i < 4; i++) {
            acc[i][0] = b1v[0]; acc[i][1] = b1v[1];
            acc[i][2] = b1v[2]; acc[i][3] = b1v[3];
        }
#pragma unroll 1
        for (int kc = 0; kc < H; kc += 4) {
            float4 a4[4];
#pragma unroll
            for (int i = 0; i < 4; i++)
                a4[i] = *reinterpret_cast<const float4*>(sH + (w * 4 + i) * H + kc);
#pragma unroll
            for (int kk = 0; kk < 4; kk++) {
                float4 bv = *reinterpret_cast<const float4*>(sW1 + (kc + kk) * H + lane * 4);
#pragma unroll
                for (int i = 0; i < 4; i++) {
                    float a = (kk == 0) ? a4[i].x : (kk == 1) ? a4[i].y
                             : (kk == 2) ? a4[i].z : a4[i].w;
                    acc[i][0] = fmaf(a, bv.x, acc[i][0]);
                    acc[i][1] = fmaf(a, bv.y, acc[i][1]);
                    acc[i][2] = fmaf(a, bv.z, acc[i][2]);
                    acc[i][3] = fmaf(a, bv.w, acc[i][3]);
                }
            }
        }

#pragma unroll
        for (int i = 0; i < 4; i++) {
            float p0 = 0.f, p1 = 0.f, p2 = 0.f;
#pragma unroll
            for (int j = 0; j < 4; j++) {
                float o = fmaxf(acc[i][j], 0.f);
                int kk = lane * 4 + j;
                p0 = fmaf(o, sW2[kk * N_OUT + 0], p0);
                p1 = fmaf(o, sW2[kk * N_OUT + 1], p1);
                p2 = fmaf(o, sW2[kk * N_OUT + 2], p2);
            }
#pragma unroll
            for (int off = 16; off > 0; off >>= 1) {
                p0 += __shfl_xor_sync(0xffffffffu, p0, off);
                p1 += __shfl_xor_sync(0xffffffffu, p1, off);
                p2 += __shfl_xor_sync(0xffffffffu, p2, off);
            }
            int n = n0 + i;
            if (lane == 0 && n < N_NODES) {
                out[(size_t)n * N_OUT + 0] = fmaxf(p0 + b2v0, 0.f);
                out[(size_t)n * N_OUT + 1] = fmaxf(p1 + b2v1, 0.f);
                out[(size_t)n * N_OUT + 2] = fmaxf(p2 + b2v2, 0.f);
            }
        }
        __syncwarp();
    }
}

// ======================= launch ============================================

extern "C" void kernel_launch(void* const* d_in, const int* in_sizes, int n_in,
                              void* d_out, int out_size) {
    const float* x       = (const float*)d_in[0];
    const int*   ei      = (const int*)d_in[1];
    const float* ea      = (const float*)d_in[2];
    const float* lin_w   = (const float*)d_in[3];
    const float* lin_b   = (const float*)d_in[4];
    const float* msg_w1  = (const float*)d_in[5];
    const float* msg_b1  = (const float*)d_in[6];
    const float* msg_w2  = (const float*)d_in[7];
    const float* msg_b2  = (const float*)d_in[8];
    const float* upd_w1  = (const float*)d_in[9];
    const float* upd_b1  = (const float*)d_in[10];
    const float* upd_w2  = (const float*)d_in[11];
    const float* upd_b2  = (const float*)d_in[12];
    const float* head_w1 = (const float*)d_in[13];
    const float* head_b1 = (const float*)d_in[14];
    const float* head_w2 = (const float*)d_in[15];
    const float* head_b2 = (const float*)d_in[16];
    float* out = (float*)d_out;

    const int* src = ei;
    const int* dst = ei + N_EDGES;

    int sm_count = 148;
    cudaDeviceGetAttribute(&sm_count, cudaDevAttrMultiProcessorCount, 0);

    const size_t smHd = (size_t)(H * H + H * N_OUT + TN * H) * sizeof(float);
    cudaFuncSetAttribute(edge_kernel, cudaFuncAttributeMaxDynamicSharedMemorySize, SM_EDGE_TOTAL);
    cudaFuncSetAttribute(node1_kernel, cudaFuncAttributeMaxDynamicSharedMemorySize, N1_TOTAL);
    cudaFuncSetAttribute(node2_kernel, cudaFuncAttributeMaxDynamicSharedMemorySize, N2_TOTAL);
    cudaFuncSetAttribute(head_kernel, cudaFuncAttributeMaxDynamicSharedMemorySize, (int)smHd);

    zero_cnt_kernel<<<(N_NODES + 255) / 256, 256>>>();
    deg_kernel<<<(N_EDGES + 255) / 256, 256>>>(dst);
    inv_kernel<<<(N_NODES + 255) / 256, 256>>>();
    lin_in_kernel<<<N_NODES, H>>>(x, lin_w, lin_b);

    for (int l = 0; l < N_LAYERS; l++) {
        zero_agg_kernel<<<1024, 256>>>();
        edge_kernel<<<sm_count, 256, SM_EDGE_TOTAL>>>(
            src, dst, ea,
            msg_w1 + (size_t)l * (H + ED) * H, msg_b1 + (size_t)l * H,
            msg_w2 + (size_t)l * H * H, msg_b2 + (size_t)l * H);
        node1_kernel<<<sm_count, 256, N1_TOTAL>>>(
            upd_w1 + (size_t)l * 2 * H * H, upd_b1 + (size_t)l * H);
        node2_kernel<<<sm_count, 256, N2_TOTAL>>>(
            upd_w2 + (size_t)l * H * H, upd_b2 + (size_t)l * H);
    }

    head_kernel<<<2 * sm_count, 256, smHd>>>(head_w1, head_b1, head_w2, head_b2, out);
}

// round 7
// speedup vs baseline: 2.3285x; 1.1847x over previous
#include <cuda_runtime.h>
#include <cuda_fp16.h>
#include <cstdint>
#include <cstddef>

// ---------------------------------------------------------------------------
// MeshGNN: N=50000, E=600000, IN=16, ED=4, H=128, L=4, OUT=3
// Round 6: fp16 hi/lo 2-pass HMMA (single weight plane), packed-fp16 h store
// (g_hp), cp.async double-buffered edge gather, dual-group pipelining.
// ---------------------------------------------------------------------------

#define N_NODES 50000
#define N_EDGES 600000
#define H 128
#define IN_F 16
#define ED 4
#define N_LAYERS 4
#define N_OUT 3
#define TN 32

#define PAD  136   // k stride (elements) for K=128 ldmatrix tiles
#define PADW 264   // k stride (elements) for K=256 W1 tile

// ---- edge kernel smem map (bytes)
#define SM_B1   0
#define SM_B2   512
#define SM_W1B  1024
#define SM_EA   3072     // + (g*2+b)*1024
#define SM_DST  7168     // + (g*2+b)*256
#define SM_W1   8192     // 34816
#define SM_W2   43008    // 34816
#define SM_A    77824    // + g*69632 + b*34816 (hi plane; lo = +17408)
#define SM_EDGE_TOTAL 217088

// ---- node1 smem map
#define N1_B1   0
#define N1_W1   1024     // 128*PADW*2 = 67584
#define N1_AH   68608    // 34816
#define N1_AL   103424
#define N1_TOTAL 138240

// ---- node2 smem map
#define N2_B2   0
#define N2_W2   1024     // 34816
#define N2_AH   35840
#define N2_AL   70656
#define N2_TOTAL 105472

__device__ float g_h[(size_t)N_NODES * H];
__device__ float g_agg[(size_t)N_NODES * H];
__device__ float g_inv[N_NODES];
__device__ uint32_t g_hp[(size_t)N_NODES * 128];  // packed fp16 h: hi[64] lo[64]
__device__ uint32_t g_u[(size_t)N_NODES * 128];   // packed fp16 U: hi[64] lo[64]

// ======================= helpers ==========================================

__device__ __forceinline__ uint32_t smem_u32(const void* p) {
    uint32_t a;
    asm("{ .reg .u64 t; cvta.to.shared.u64 t, %1; cvt.u32.u64 %0, t; }"
        : "=r"(a) : "l"(p));
    return a;
}

__device__ __forceinline__ void ldsm_x4(uint32_t* r, uint32_t addr) {
    asm volatile("ldmatrix.sync.aligned.m8n8.x4.shared.b16 {%0,%1,%2,%3}, [%4];"
                 : "=r"(r[0]), "=r"(r[1]), "=r"(r[2]), "=r"(r[3]) : "r"(addr));
}

__device__ __forceinline__ void mma16816(float* c, const uint32_t* a,
                                         uint32_t b0, uint32_t b1) {
    asm volatile(
        "mma.sync.aligned.m16n8k16.row.col.f32.f16.f16.f32 "
        "{%0,%1,%2,%3}, {%4,%5,%6,%7}, {%8,%9}, {%0,%1,%2,%3};"
        : "+f"(c[0]), "+f"(c[1]), "+f"(c[2]), "+f"(c[3])
        : "r"(a[0]), "r"(a[1]), "r"(a[2]), "r"(a[3]), "r"(b0), "r"(b1));
}

// split (x,y) into packed fp16x2 hi and lo(residual) words
__device__ __forceinline__ void hilo2h(float x, float y, uint32_t& hi, uint32_t& lo) {
    __half hx = __float2half(x), hy = __float2half(y);
    __half2 hp = __halves2half2(hx, hy);
    hi = *reinterpret_cast<uint32_t*>(&hp);
    __half lx = __float2half(x - __half2float(hx));
    __half ly = __float2half(y - __half2float(hy));
    __half2 lp = __halves2half2(lx, ly);
    lo = *reinterpret_cast<uint32_t*>(&lp);
}

#define GROUP_BAR(gid) \
    asm volatile("bar.sync %0, %1;" :: "r"(1 + (gid)), "r"(128) : "memory")

#define CP_ASYNC16(dst, src) \
    asm volatile("cp.async.ca.shared.global [%0], [%1], 16;" :: "r"(dst), "l"(src) : "memory")
#define CP_ASYNC4(dst, src) \
    asm volatile("cp.async.ca.shared.global [%0], [%1], 4;" :: "r"(dst), "l"(src) : "memory")
#define CP_COMMIT() asm volatile("cp.async.commit_group;" ::: "memory")
#define CP_WAIT0()  asm volatile("cp.async.wait_group 0;" ::: "memory")

// ======================= small helper kernels ==============================

__global__ void zero_agg_kernel() {
    size_t i = (size_t)blockIdx.x * blockDim.x + threadIdx.x;
    const size_t n4 = (size_t)N_NODES * H / 4;
    float4 z = make_float4(0.f, 0.f, 0.f, 0.f);
    for (; i < n4; i += (size_t)gridDim.x * blockDim.x)
        reinterpret_cast<float4*>(g_agg)[i] = z;
}

__global__ void zero_cnt_kernel() {
    int i = blockIdx.x * blockDim.x + threadIdx.x;
    if (i < N_NODES) g_inv[i] = 0.f;
}

__global__ void deg_kernel(const int* __restrict__ dst) {
    int e = blockIdx.x * blockDim.x + threadIdx.x;
    if (e < N_EDGES) atomicAdd(&g_inv[dst[e]], 1.0f);
}

__global__ void inv_kernel() {
    int i = blockIdx.x * blockDim.x + threadIdx.x;
    if (i < N_NODES) g_inv[i] = 1.0f / fmaxf(g_inv[i], 1.0f);
}

// h = relu(x @ W + b); also writes packed fp16 hi/lo planes to g_hp
__global__ void lin_in_kernel(const float* __restrict__ x,
                              const float* __restrict__ W,
                              const float* __restrict__ b) {
    __shared__ float sx[IN_F];
    __shared__ float sh[H];
    int n = blockIdx.x;
    if (threadIdx.x < IN_F) sx[threadIdx.x] = x[(size_t)n * IN_F + threadIdx.x];
    __syncthreads();
    int c = threadIdx.x;
    float acc = __ldg(&b[c]);
#pragma unroll
    for (int k = 0; k < IN_F; k++)
        acc = fmaf(sx[k], __ldg(&W[k * H + c]), acc);
    float v = fmaxf(acc, 0.f);
    g_h[(size_t)n * H + c] = v;
    sh[c] = v;
    __syncthreads();
    if (threadIdx.x < 64) {
        int w = threadIdx.x;
        uint32_t hi, lo;
        hilo2h(sh[2 * w], sh[2 * w + 1], hi, lo);
        g_hp[(size_t)n * 128 + w]      = hi;
        g_hp[(size_t)n * 128 + 64 + w] = lo;
    }
}

// stage W[k][n] fp32 transposed into WT[n][k] single fp16 plane, stride pad
__device__ __forceinline__ void stage_w_f16(char* smem, const float* __restrict__ W,
                                            int off, int kdim, int pad) {
    for (int idx = threadIdx.x; idx < kdim * H; idx += blockDim.x) {
        int k = idx >> 7, n = idx & 127;
        *reinterpret_cast<__half*>(smem + off + (n * pad + k) * 2) = __float2half(W[idx]);
    }
}

// ======================= edge kernel =======================================
// 256 thr = 2 groups x 4 warps; 64-edge tiles per group, double-buffered A
// via cp.async from packed g_hp. fp16 2-pass (A hi/lo, single W plane).

__device__ __forceinline__ void edge_prefetch(
    char* smem, uint32_t sb, int g, int b, int e0, int srcval, int ltid,
    const float* __restrict__ ea, const int* __restrict__ dst) {
    const int r  = ltid >> 1;
    const int hc = (ltid & 1) * 64;
    const uint32_t* sp = g_hp + (size_t)srcval * 128 + (hc >> 1);
    uint32_t dh = sb + SM_A + (uint32_t)g * 69632u + (uint32_t)b * 34816u +
                  (uint32_t)(r * PAD + hc) * 2u;
    uint32_t dl = dh + 17408u;
#pragma unroll
    for (int p = 0; p < 8; p++) CP_ASYNC16(dh + 16u * p, sp + 4 * p);
#pragma unroll
    for (int p = 0; p < 8; p++) CP_ASYNC16(dl + 16u * p, sp + 64 + 4 * p);
    if (ltid < 64) {
        CP_ASYNC16(sb + SM_EA + (uint32_t)(g * 2 + b) * 1024u + (uint32_t)ltid * 16u,
                   ea + (size_t)(e0 + ltid) * 4);
        CP_ASYNC4(sb + SM_DST + (uint32_t)(g * 2 + b) * 256u + (uint32_t)ltid * 4u,
                  dst + e0 + ltid);
    }
}

__global__ void __launch_bounds__(256, 1)
edge_kernel(const int* __restrict__ src, const int* __restrict__ dst,
            const float* __restrict__ ea,
            const float* __restrict__ W1, const float* __restrict__ b1,
            const float* __restrict__ W2, const float* __restrict__ b2) {
    extern __shared__ char smem[];
    const uint32_t sb = smem_u32(smem);
    float* s_b1  = reinterpret_cast<float*>(smem + SM_B1);
    float* s_b2  = reinterpret_cast<float*>(smem + SM_B2);
    float* s_w1b = reinterpret_cast<float*>(smem + SM_W1B);

    const int tid  = threadIdx.x;
    const int wid  = tid >> 5;
    const int lane = tid & 31;
    const int g    = wid >> 2;
    const int lw   = wid & 3;
    const int ltid = tid & 127;

    stage_w_f16(smem, W1, SM_W1, H, PAD);
    stage_w_f16(smem, W2, SM_W2, H, PAD);
    if (tid < 128) {
        s_b1[tid] = b1[tid];
        s_b2[tid] = b2[tid];
#pragma unroll
        for (int j = 0; j < 4; j++) s_w1b[j * 128 + tid] = W1[(H + j) * H + tid];
    }
    __syncthreads();

    const int m0 = lw * 16;
    const int rq = lane >> 2;
    const int cp = (lane & 3) * 2;
    const uint32_t aOffLane = ((uint32_t)(m0 + (lane & 15)) * PAD + 8u * (lane >> 4)) * 2u;
    const uint32_t bOffLane = ((uint32_t)((lane & 7) + 8 * ((lane >> 3) & 1)) * PAD +
                               8u * (lane >> 4)) * 2u;

    const int NT = N_EDGES / 64;  // 9375
    const int stride = gridDim.x * 2;
    int t = blockIdx.x * 2 + g;
    int buf = 0;
    int nsrc = 0;

    if (t < NT) {
        nsrc = __ldg(&src[t * 64 + (ltid >> 1)]);
        edge_prefetch(smem, sb, g, 0, t * 64, nsrc, ltid, ea, dst);
        CP_COMMIT();
        int t2 = t + stride;
        nsrc = (t2 < NT) ? __ldg(&src[t2 * 64 + (ltid >> 1)]) : 0;
    }

    for (; t < NT; t += stride) {
        CP_WAIT0();
        GROUP_BAR(g);

        const int tn = t + stride;
        if (tn < NT) {
            edge_prefetch(smem, sb, g, buf ^ 1, tn * 64, nsrc, ltid, ea, dst);
            CP_COMMIT();
            const int tnn = tn + stride;
            if (tnn < NT) nsrc = __ldg(&src[tnn * 64 + (ltid >> 1)]);
        }

        const uint32_t bAH = sb + SM_A + (uint32_t)g * 69632u + (uint32_t)buf * 34816u;
        const uint32_t bAL = bAH + 17408u;
        float* s_ea  = reinterpret_cast<float*>(smem + SM_EA + (g * 2 + buf) * 1024);
        int*   s_dst = reinterpret_cast<int*>(smem + SM_DST + (g * 2 + buf) * 256);

        // ---- acc init: b1 + ea @ W1b
        float acc[16][4];
        {
            float ea0[4], ea1[4];
#pragma unroll
            for (int i = 0; i < 4; i++) {
                ea0[i] = s_ea[(m0 + rq) * 4 + i];
                ea1[i] = s_ea[(m0 + rq + 8) * 4 + i];
            }
#pragma unroll
            for (int j = 0; j < 16; j++) {
                const int n = j * 8 + cp;
                float a0 = s_b1[n], a1 = s_b1[n + 1];
                float a2 = a0, a3 = a1;
#pragma unroll
                for (int i = 0; i < 4; i++) {
                    float w0 = s_w1b[i * 128 + n], w1 = s_w1b[i * 128 + n + 1];
                    a0 = fmaf(ea0[i], w0, a0);
                    a1 = fmaf(ea0[i], w1, a1);
                    a2 = fmaf(ea1[i], w0, a2);
                    a3 = fmaf(ea1[i], w1, a3);
                }
                acc[j][0] = a0; acc[j][1] = a1; acc[j][2] = a2; acc[j][3] = a3;
            }
        }

        // ---- GEMM1 (fp16 2-pass: Ah*B + Al*B)
#pragma unroll
        for (int ks = 0; ks < 8; ks++) {
            const uint32_t k0b = (uint32_t)(ks * 16) * 2u;
            uint32_t ah[4], al[4];
            ldsm_x4(ah, bAH + aOffLane + k0b);
            ldsm_x4(al, bAL + aOffLane + k0b);
#pragma unroll
            for (int jj = 0; jj < 8; jj++) {
                const uint32_t bo = bOffLane + k0b + (uint32_t)jj * (16 * PAD * 2);
                uint32_t bh[4];
                ldsm_x4(bh, sb + SM_W1 + bo);
                mma16816(acc[2 * jj],     ah, bh[0], bh[2]);
                mma16816(acc[2 * jj + 1], ah, bh[1], bh[3]);
                mma16816(acc[2 * jj],     al, bh[0], bh[2]);
                mma16816(acc[2 * jj + 1], al, bh[1], bh[3]);
            }
        }

        // ---- relu + register re-split (fp16 hi/lo A frags for GEMM2)
        uint32_t a2h[8][4], a2l[8][4];
#pragma unroll
        for (int gg = 0; gg < 8; gg++) {
            float c0 = fmaxf(acc[2 * gg][0], 0.f),     c1 = fmaxf(acc[2 * gg][1], 0.f);
            float c2 = fmaxf(acc[2 * gg][2], 0.f),     c3 = fmaxf(acc[2 * gg][3], 0.f);
            float d0 = fmaxf(acc[2 * gg + 1][0], 0.f), d1 = fmaxf(acc[2 * gg + 1][1], 0.f);
            float d2 = fmaxf(acc[2 * gg + 1][2], 0.f), d3 = fmaxf(acc[2 * gg + 1][3], 0.f);
            hilo2h(c0, c1, a2h[gg][0], a2l[gg][0]);
            hilo2h(c2, c3, a2h[gg][1], a2l[gg][1]);
            hilo2h(d0, d1, a2h[gg][2], a2l[gg][2]);
            hilo2h(d2, d3, a2h[gg][3], a2l[gg][3]);
        }

#pragma unroll
        for (int j = 0; j < 16; j++) {
            const int n = j * 8 + cp;
            acc[j][0] = s_b2[n]; acc[j][1] = s_b2[n + 1];
            acc[j][2] = s_b2[n]; acc[j][3] = s_b2[n + 1];
        }

        // ---- GEMM2 (fp16 2-pass)
#pragma unroll
        for (int ks = 0; ks < 8; ks++) {
            const uint32_t k0b = (uint32_t)(ks * 16) * 2u;
#pragma unroll
            for (int jj = 0; jj < 8; jj++) {
                const uint32_t bo = bOffLane + k0b + (uint32_t)jj * (16 * PAD * 2);
                uint32_t bh[4];
                ldsm_x4(bh, sb + SM_W2 + bo);
                mma16816(acc[2 * jj],     a2h[ks], bh[0], bh[2]);
                mma16816(acc[2 * jj + 1], a2h[ks], bh[1], bh[3]);
                mma16816(acc[2 * jj],     a2l[ks], bh[0], bh[2]);
                mma16816(acc[2 * jj + 1], a2l[ks], bh[1], bh[3]);
            }
        }

        // ---- relu + float2 atomic scatter
        {
            const int r0 = m0 + rq, r1 = r0 + 8;
            float* p0 = g_agg + (size_t)s_dst[r0] * H;
            float* p1 = g_agg + (size_t)s_dst[r1] * H;
#pragma unroll
            for (int j = 0; j < 16; j++) {
                const int n = j * 8 + cp;
                atomicAdd(reinterpret_cast<float2*>(p0 + n),
                          make_float2(fmaxf(acc[j][0], 0.f), fmaxf(acc[j][1], 0.f)));
                atomicAdd(reinterpret_cast<float2*>(p1 + n),
                          make_float2(fmaxf(acc[j][2], 0.f), fmaxf(acc[j][3], 0.f)));
            }
        }
        buf ^= 1;
    }
}

// ======================= node1: U = relu([h|agg/cnt]@W1 + b1) ==============
// fp16 2-pass, K=256 as two K=128 phases; phase0 A copied from packed g_hp.

__global__ void __launch_bounds__(256, 1)
node1_kernel(const float* __restrict__ W1, const float* __restrict__ b1) {
    extern __shared__ char smem[];
    const uint32_t sb = smem_u32(smem);
    float* s_b1 = reinterpret_cast<float*>(smem + N1_B1);

    const int tid  = threadIdx.x;
    const int wid  = tid >> 5;
    const int lane = tid & 31;

    stage_w_f16(smem, W1, N1_W1, 2 * H, PADW);
    if (tid < 128) s_b1[tid] = b1[tid];
    __syncthreads();

    const int m0 = wid * 16;
    const int rq = lane >> 2;
    const int cp = (lane & 3) * 2;
    const uint32_t aOffLane = ((uint32_t)(m0 + (lane & 15)) * PAD + 8u * (lane >> 4)) * 2u;
    const uint32_t bOffLane = ((uint32_t)((lane & 7) + 8 * ((lane >> 3) & 1)) * PADW +
                               8u * (lane >> 4)) * 2u;

    const int NTN = (N_NODES + 127) / 128;

    for (int t = blockIdx.x; t < NTN; t += gridDim.x) {
        float acc[16][4];
#pragma unroll
        for (int j = 0; j < 16; j++) {
            const int n = j * 8 + cp;
            acc[j][0] = s_b1[n]; acc[j][1] = s_b1[n + 1];
            acc[j][2] = s_b1[n]; acc[j][3] = s_b1[n + 1];
        }

#pragma unroll 1
        for (int phase = 0; phase < 2; phase++) {
            if (phase == 0) {
                // A = h: pure copy from packed g_hp
                for (int i = tid; i < 128 * 64; i += 256) {
                    const int r = i >> 6, w = i & 63;
                    const int node = t * 128 + r;
                    uint32_t hi = 0, lo = 0;
                    if (node < N_NODES) {
                        hi = g_hp[(size_t)node * 128 + w];
                        lo = g_hp[(size_t)node * 128 + 64 + w];
                    }
                    const int o = (r * PAD + 2 * w) * 2;
                    *reinterpret_cast<uint32_t*>(smem + N1_AH + o) = hi;
                    *reinterpret_cast<uint32_t*>(smem + N1_AL + o) = lo;
                }
            } else {
                // A = agg * inv: convert
                const int r = tid >> 1;
                const int hc = (tid & 1) * 64;
                const int node = t * 128 + r;
                const bool v = (node < N_NODES);
                const float* hp = g_agg + (size_t)(v ? node : 0) * H + hc;
                const float sc = v ? __ldg(&g_inv[node]) : 0.f;
                char* dh = smem + N1_AH + (r * PAD + hc) * 2;
                char* dl = smem + N1_AL + (r * PAD + hc) * 2;
#pragma unroll
                for (int p = 0; p < 8; p++) {
                    float4 v0 = v ? *reinterpret_cast<const float4*>(hp + 8 * p)
                                  : make_float4(0.f, 0.f, 0.f, 0.f);
                    float4 v1 = v ? *reinterpret_cast<const float4*>(hp + 8 * p + 4)
                                  : make_float4(0.f, 0.f, 0.f, 0.f);
                    uint4 wh, wl;
                    hilo2h(v0.x * sc, v0.y * sc, wh.x, wl.x);
                    hilo2h(v0.z * sc, v0.w * sc, wh.y, wl.y);
                    hilo2h(v1.x * sc, v1.y * sc, wh.z, wl.z);
                    hilo2h(v1.z * sc, v1.w * sc, wh.w, wl.w);
                    *reinterpret_cast<uint4*>(dh + p * 16) = wh;
                    *reinterpret_cast<uint4*>(dl + p * 16) = wl;
                }
            }
            __syncthreads();

            const uint32_t kbase = (uint32_t)(phase * 128) * 2u;
#pragma unroll
            for (int ks = 0; ks < 8; ks++) {
                const uint32_t k0a = (uint32_t)(ks * 16) * 2u;
                const uint32_t k0b = kbase + k0a;
                uint32_t ah[4], al[4];
                ldsm_x4(ah, sb + N1_AH + aOffLane + k0a);
                ldsm_x4(al, sb + N1_AL + aOffLane + k0a);
#pragma unroll
                for (int jj = 0; jj < 8; jj++) {
                    const uint32_t bo = bOffLane + k0b + (uint32_t)jj * (16 * PADW * 2);
                    uint32_t bh[4];
                    ldsm_x4(bh, sb + N1_W1 + bo);
                    mma16816(acc[2 * jj],     ah, bh[0], bh[2]);
                    mma16816(acc[2 * jj + 1], ah, bh[1], bh[3]);
                    mma16816(acc[2 * jj],     al, bh[0], bh[2]);
                    mma16816(acc[2 * jj + 1], al, bh[1], bh[3]);
                }
            }
            __syncthreads();
        }

        // epilogue: relu -> packed fp16 hi/lo -> g_u
        {
            const int r0 = m0 + rq, r1 = r0 + 8;
            const int n0 = t * 128 + r0, n1 = t * 128 + r1;
            const int wq = lane & 3;
#pragma unroll
            for (int j = 0; j < 16; j++) {
                const int w = j * 4 + wq;
                uint32_t hi0, lo0, hi1, lo1;
                hilo2h(fmaxf(acc[j][0], 0.f), fmaxf(acc[j][1], 0.f), hi0, lo0);
                hilo2h(fmaxf(acc[j][2], 0.f), fmaxf(acc[j][3], 0.f), hi1, lo1);
                if (n0 < N_NODES) {
                    g_u[(size_t)n0 * 128 + w]      = hi0;
                    g_u[(size_t)n0 * 128 + 64 + w] = lo0;
                }
                if (n1 < N_NODES) {
                    g_u[(size_t)n1 * 128 + w]      = hi1;
                    g_u[(size_t)n1 * 128 + 64 + w] = lo1;
                }
            }
        }
    }
}

// ======================= node2: h = relu(U@W2 + b2 + h) ====================

__global__ void __launch_bounds__(256, 1)
node2_kernel(const float* __restrict__ W2, const float* __restrict__ b2) {
    extern __shared__ char smem[];
    const uint32_t sb = smem_u32(smem);
    float* s_b2 = reinterpret_cast<float*>(smem + N2_B2);

    const int tid  = threadIdx.x;
    const int wid  = tid >> 5;
    const int lane = tid & 31;

    stage_w_f16(smem, W2, N2_W2, H, PAD);
    if (tid < 128) s_b2[tid] = b2[tid];
    __syncthreads();

    const int m0 = wid * 16;
    const int rq = lane >> 2;
    const int cp = (lane & 3) * 2;
    const uint32_t aOffLane = ((uint32_t)(m0 + (lane & 15)) * PAD + 8u * (lane >> 4)) * 2u;
    const uint32_t bOffLane = ((uint32_t)((lane & 7) + 8 * ((lane >> 3) & 1)) * PAD +
                               8u * (lane >> 4)) * 2u;

    const int NTN = (N_NODES + 127) / 128;

    for (int t = blockIdx.x; t < NTN; t += gridDim.x) {
        for (int i = tid; i < 128 * 64; i += 256) {
            const int r = i >> 6, w = i & 63;
            const int node = t * 128 + r;
            uint32_t hi = 0, lo = 0;
            if (node < N_NODES) {
                hi = g_u[(size_t)node * 128 + w];
                lo = g_u[(size_t)node * 128 + 64 + w];
            }
            const int o = (r * PAD + 2 * w) * 2;
            *reinterpret_cast<uint32_t*>(smem + N2_AH + o) = hi;
            *reinterpret_cast<uint32_t*>(smem + N2_AL + o) = lo;
        }
        __syncthreads();

        float acc[16][4];
#pragma unroll
        for (int j = 0; j < 16; j++) {
            const int n = j * 8 + cp;
            acc[j][0] = s_b2[n]; acc[j][1] = s_b2[n + 1];
            acc[j][2] = s_b2[n]; acc[j][3] = s_b2[n + 1];
        }

#pragma unroll
        for (int ks = 0; ks < 8; ks++) {
            const uint32_t k0b = (uint32_t)(ks * 16) * 2u;
            uint32_t ah[4], al[4];
            ldsm_x4(ah, sb + N2_AH + aOffLane + k0b);
            ldsm_x4(al, sb + N2_AL + aOffLane + k0b);
#pragma unroll
            for (int jj = 0; jj < 8; jj++) {
                const uint32_t bo = bOffLane + k0b + (uint32_t)jj * (16 * PAD * 2);
                uint32_t bh[4];
                ldsm_x4(bh, sb + N2_W2 + bo);
                mma16816(acc[2 * jj],     ah, bh[0], bh[2]);
                mma16816(acc[2 * jj + 1], ah, bh[1], bh[3]);
                mma16816(acc[2 * jj],     al, bh[0], bh[2]);
                mma16816(acc[2 * jj + 1], al, bh[1], bh[3]);
            }
        }

        // epilogue: + h residual, relu, write g_h fp32 + packed g_hp
        {
            const int r0 = m0 + rq, r1 = r0 + 8;
            const int n0 = t * 128 + r0, n1 = t * 128 + r1;
#pragma unroll
            for (int j = 0; j < 16; j++) {
                const int n = j * 8 + cp;
                const int w = n >> 1;
                if (n0 < N_NODES) {
                    float2 h0 = *reinterpret_cast<const float2*>(g_h + (size_t)n0 * H + n);
                    float2 o0 = make_float2(fmaxf(acc[j][0] + h0.x, 0.f),
                                            fmaxf(acc[j][1] + h0.y, 0.f));
                    *reinterpret_cast<float2*>(g_h + (size_t)n0 * H + n) = o0;
                    uint32_t hi, lo;
                    hilo2h(o0.x, o0.y, hi, lo);
                    g_hp[(size_t)n0 * 128 + w]      = hi;
                    g_hp[(size_t)n0 * 128 + 64 + w] = lo;
                }
                if (n1 < N_NODES) {
                    float2 h1 = *reinterpret_cast<const float2*>(g_h + (size_t)n1 * H + n);
                    float2 o1 = make_float2(fmaxf(acc[j][2] + h1.x, 0.f),
                                            fmaxf(acc[j][3] + h1.y, 0.f));
                    *reinterpret_cast<float2*>(g_h + (size_t)n1 * H + n) = o1;
                    uint32_t hi, lo;
                    hilo2h(o1.x, o1.y, hi, lo);
                    g_hp[(size_t)n1 * 128 + w]      = hi;
                    g_hp[(size_t)n1 * 128 + 64 + w] = lo;
                }
            }
        }
        __syncthreads();
    }
}

// ======================= head ==============================================

__global__ void __launch_bounds__(256, 1)
head_kernel(const float* __restrict__ W1, const float* __restrict__ b1,
            const float* __restrict__ W2, const float* __restrict__ b2,
            float* __restrict__ out) {
    extern __shared__ float sm[];
    float* sW1 = sm;
    float* sW2 = sW1 + H * H;
    float* sH  = sW2 + H * N_OUT;

    for (int i = threadIdx.x; i < H * H; i += 256) sW1[i] = W1[i];
    for (int i = threadIdx.x; i < H * N_OUT; i += 256) sW2[i] = W2[i];

    const int lane = threadIdx.x & 31;
    const int w    = threadIdx.x >> 5;
    float b1v[4];
#pragma unroll
    for (int j = 0; j < 4; j++) b1v[j] = __ldg(&b1[lane * 4 + j]);
    const float b2v0 = __ldg(&b2[0]), b2v1 = __ldg(&b2[1]), b2v2 = __ldg(&b2[2]);
    __syncthreads();

    const int ntiles = (N_NODES + TN - 1) / TN;
    for (int t = blockIdx.x; t < ntiles; t += gridDim.x) {
        const int n0 = t * TN + w * 4;
#pragma unroll
        for (int i = 0; i < 4; i++) {
            int n = n0 + i;
            float4 hv = make_float4(0.f, 0.f, 0.f, 0.f);
            if (n < N_NODES)
                hv = *reinterpret_cast<const float4*>(g_h + (size_t)n * H + lane * 4);
            *reinterpret_cast<float4*>(sH + (w * 4 + i) * H + lane * 4) = hv;
        }
        __syncwarp();

        float acc[4][4];
#pragma unroll
        for (int i = 0; i < 4; i++) {
            acc[i][0] = b1v[0]; acc[i][1] = b1v[1];
            acc[i][2] = b1v[2]; acc[i][3] = b1v[3];
        }
#pragma unroll 1
        for (int kc = 0; kc < H; kc += 4) {
            float4 a4[4];
#pragma unroll
            for (int i = 0; i < 4; i++)
                a4[i] = *reinterpret_cast<const float4*>(sH + (w * 4 + i) * H + kc);
#pragma unroll
            for (int kk = 0; kk < 4; kk++) {
                float4 bv = *reinterpret_cast<const float4*>(sW1 + (kc + kk) * H + lane * 4);
#pragma unroll
                for (int i = 0; i < 4; i++) {
                    float a = (kk == 0) ? a4[i].x : (kk == 1) ? a4[i].y
                             : (kk == 2) ? a4[i].z : a4[i].w;
                    acc[i][0] = fmaf(a, bv.x, acc[i][0]);
                    acc[i][1] = fmaf(a, bv.y, acc[i][1]);
                    acc[i][2] = fmaf(a, bv.z, acc[i][2]);
                    acc[i][3] = fmaf(a, bv.w, acc[i][3]);
                }
            }
        }

#pragma unroll
        for (int i = 0; i < 4; i++) {
            float p0 = 0.f, p1 = 0.f, p2 = 0.f;
#pragma unroll
            for (int j = 0; j < 4; j++) {
                float o = fmaxf(acc[i][j], 0.f);
                int kk = lane * 4 + j;
                p0 = fmaf(o, sW2[kk * N_OUT + 0], p0);
                p1 = fmaf(o, sW2[kk * N_OUT + 1], p1);
                p2 = fmaf(o, sW2[kk * N_OUT + 2], p2);
            }
#pragma unroll
            for (int off = 16; off > 0; off >>= 1) {
                p0 += __shfl_xor_sync(0xffffffffu, p0, off);
                p1 += __shfl_xor_sync(0xffffffffu, p1, off);
                p2 += __shfl_xor_sync(0xffffffffu, p2, off);
            }
            int n = n0 + i;
            if (lane == 0 && n < N_NODES) {
                out[(size_t)n * N_OUT + 0] = fmaxf(p0 + b2v0, 0.f);
                out[(size_t)n * N_OUT + 1] = fmaxf(p1 + b2v1, 0.f);
                out[(size_t)n * N_OUT + 2] = fmaxf(p2 + b2v2, 0.f);
            }
        }
        __syncwarp();
    }
}

// ======================= launch ============================================

extern "C" void kernel_launch(void* const* d_in, const int* in_sizes, int n_in,
                              void* d_out, int out_size) {
    const float* x       = (const float*)d_in[0];
    const int*   ei      = (const int*)d_in[1];
    const float* ea      = (const float*)d_in[2];
    const float* lin_w   = (const float*)d_in[3];
    const float* lin_b   = (const float*)d_in[4];
    const float* msg_w1  = (const float*)d_in[5];
    const float* msg_b1  = (const float*)d_in[6];
    const float* msg_w2  = (const float*)d_in[7];
    const float* msg_b2  = (const float*)d_in[8];
    const float* upd_w1  = (const float*)d_in[9];
    const float* upd_b1  = (const float*)d_in[10];
    const float* upd_w2  = (const float*)d_in[11];
    const float* upd_b2  = (const float*)d_in[12];
    const float* head_w1 = (const float*)d_in[13];
    const float* head_b1 = (const float*)d_in[14];
    const float* head_w2 = (const float*)d_in[15];
    const float* head_b2 = (const float*)d_in[16];
    float* out = (float*)d_out;

    const int* src = ei;
    const int* dst = ei + N_EDGES;

    int sm_count = 148;
    cudaDeviceGetAttribute(&sm_count, cudaDevAttrMultiProcessorCount, 0);

    const size_t smHd = (size_t)(H * H + H * N_OUT + TN * H) * sizeof(float);
    cudaFuncSetAttribute(edge_kernel, cudaFuncAttributeMaxDynamicSharedMemorySize, SM_EDGE_TOTAL);
    cudaFuncSetAttribute(node1_kernel, cudaFuncAttributeMaxDynamicSharedMemorySize, N1_TOTAL);
    cudaFuncSetAttribute(node2_kernel, cudaFuncAttributeMaxDynamicSharedMemorySize, N2_TOTAL);
    cudaFuncSetAttribute(head_kernel, cudaFuncAttributeMaxDynamicSharedMemorySize, (int)smHd);

    zero_cnt_kernel<<<(N_NODES + 255) / 256, 256>>>();
    deg_kernel<<<(N_EDGES + 255) / 256, 256>>>(dst);
    inv_kernel<<<(N_NODES + 255) / 256, 256>>>();
    lin_in_kernel<<<N_NODES, H>>>(x, lin_w, lin_b);

    for (int l = 0; l < N_LAYERS; l++) {
        zero_agg_kernel<<<1024, 256>>>();
        edge_kernel<<<sm_count, 256, SM_EDGE_TOTAL>>>(
            src, dst, ea,
            msg_w1 + (size_t)l * (H + ED) * H, msg_b1 + (size_t)l * H,
            msg_w2 + (size_t)l * H * H, msg_b2 + (size_t)l * H);
        node1_kernel<<<sm_count, 256, N1_TOTAL>>>(
            upd_w1 + (size_t)l * 2 * H * H, upd_b1 + (size_t)l * H);
        node2_kernel<<<sm_count, 256, N2_TOTAL>>>(
            upd_w2 + (size_t)l * H * H, upd_b2 + (size_t)l * H);
    }

    head_kernel<<<2 * sm_count, 256, smHd>>>(head_w1, head_b1, head_w2, head_b2, out);
}

// round 8
// speedup vs baseline: 2.9251x; 1.2562x over previous
#include <cuda_runtime.h>
#include <cuda_fp16.h>
#include <cstdint>
#include <cstddef>

// ---------------------------------------------------------------------------
// MeshGNN: N=50000, E=600000, IN=16, ED=4, H=128, L=4, OUT=3
// Round 7: single-pass fp16 edge MLPs (A hi-plane only), ea folded into the
// MMA as k-columns 128..143 (EPAD=152 tiles), agg-zeroing fused into node1.
// Node kernels remain fp16 2-pass.
// ---------------------------------------------------------------------------

#define N_NODES 50000
#define N_EDGES 600000
#define H 128
#define IN_F 16
#define ED 4
#define N_LAYERS 4
#define N_OUT 3
#define TN 32

#define PAD  136   // node kernels: k stride (elements)
#define PADW 264   // node1 W1 (K=256) stride
#define EPAD 152   // edge kernel stride: 128 ch + 16 ea block + 8 slack

#define A_BUF  19456   // 64 * EPAD * 2
#define W_TILE 38912   // 128 * EPAD * 2

// ---- edge kernel smem map (bytes)
#define SM_B1   0
#define SM_B2   512
#define SM_DST  1024     // + (g*2+b)*256, 4 bufs
#define SM_W1   4096     // 38912 (includes ea rows at k=128..143)
#define SM_W2   43008    // 38912
#define SM_A    81920    // + (g*2+b)*19456
#define SM_EDGE_TOTAL 159744

// ---- node1 smem map
#define N1_B1   0
#define N1_W1   1024     // 128*PADW*2 = 67584
#define N1_AH   68608
#define N1_AL   103424
#define N1_TOTAL 138240

// ---- node2 smem map
#define N2_B2   0
#define N2_W2   1024
#define N2_AH   35840
#define N2_AL   70656
#define N2_TOTAL 105472

__device__ float g_h[(size_t)N_NODES * H];
__device__ float g_agg[(size_t)N_NODES * H];
__device__ float g_inv[N_NODES];
__device__ uint32_t g_hp[(size_t)N_NODES * 128];   // packed fp16 h: hi[64] lo[64]
__device__ uint32_t g_u[(size_t)N_NODES * 128];    // packed fp16 U: hi[64] lo[64]
__device__ uint32_t g_eap[(size_t)N_EDGES * 8];    // fp16 ea block (4 real + 12 zero)

// ======================= helpers ==========================================

__device__ __forceinline__ uint32_t smem_u32(const void* p) {
    uint32_t a;
    asm("{ .reg .u64 t; cvta.to.shared.u64 t, %1; cvt.u32.u64 %0, t; }"
        : "=r"(a) : "l"(p));
    return a;
}

__device__ __forceinline__ void ldsm_x4(uint32_t* r, uint32_t addr) {
    asm volatile("ldmatrix.sync.aligned.m8n8.x4.shared.b16 {%0,%1,%2,%3}, [%4];"
                 : "=r"(r[0]), "=r"(r[1]), "=r"(r[2]), "=r"(r[3]) : "r"(addr));
}

__device__ __forceinline__ void mma16816(float* c, const uint32_t* a,
                                         uint32_t b0, uint32_t b1) {
    asm volatile(
        "mma.sync.aligned.m16n8k16.row.col.f32.f16.f16.f32 "
        "{%0,%1,%2,%3}, {%4,%5,%6,%7}, {%8,%9}, {%0,%1,%2,%3};"
        : "+f"(c[0]), "+f"(c[1]), "+f"(c[2]), "+f"(c[3])
        : "r"(a[0]), "r"(a[1]), "r"(a[2]), "r"(a[3]), "r"(b0), "r"(b1));
}

__device__ __forceinline__ uint32_t packh2(float x, float y) {
    __half2 h = __floats2half2_rn(x, y);
    return *reinterpret_cast<uint32_t*>(&h);
}

// split (x,y) into packed fp16x2 hi and lo(residual) words
__device__ __forceinline__ void hilo2h(float x, float y, uint32_t& hi, uint32_t& lo) {
    __half hx = __float2half(x), hy = __float2half(y);
    __half2 hp = __halves2half2(hx, hy);
    hi = *reinterpret_cast<uint32_t*>(&hp);
    __half lx = __float2half(x - __half2float(hx));
    __half ly = __float2half(y - __half2float(hy));
    __half2 lp = __halves2half2(lx, ly);
    lo = *reinterpret_cast<uint32_t*>(&lp);
}

#define GROUP_BAR(gid) \
    asm volatile("bar.sync %0, %1;" :: "r"(1 + (gid)), "r"(128) : "memory")

#define CP_ASYNC16(dst, src) \
    asm volatile("cp.async.ca.shared.global [%0], [%1], 16;" :: "r"(dst), "l"(src) : "memory")
#define CP_ASYNC4(dst, src) \
    asm volatile("cp.async.ca.shared.global [%0], [%1], 4;" :: "r"(dst), "l"(src) : "memory")
#define CP_COMMIT() asm volatile("cp.async.commit_group;" ::: "memory")
#define CP_WAIT0()  asm volatile("cp.async.wait_group 0;" ::: "memory")

// ======================= small helper kernels ==============================

__global__ void zero_agg_kernel() {
    size_t i = (size_t)blockIdx.x * blockDim.x + threadIdx.x;
    const size_t n4 = (size_t)N_NODES * H / 4;
    float4 z = make_float4(0.f, 0.f, 0.f, 0.f);
    for (; i < n4; i += (size_t)gridDim.x * blockDim.x)
        reinterpret_cast<float4*>(g_agg)[i] = z;
}

__global__ void zero_cnt_kernel() {
    int i = blockIdx.x * blockDim.x + threadIdx.x;
    if (i < N_NODES) g_inv[i] = 0.f;
}

__global__ void deg_kernel(const int* __restrict__ dst) {
    int e = blockIdx.x * blockDim.x + threadIdx.x;
    if (e < N_EDGES) atomicAdd(&g_inv[dst[e]], 1.0f);
}

__global__ void inv_kernel() {
    int i = blockIdx.x * blockDim.x + threadIdx.x;
    if (i < N_NODES) g_inv[i] = 1.0f / fmaxf(g_inv[i], 1.0f);
}

// pack ea into fp16 k-block (4 real + 12 zeros = 16 halves = 8 words)
__global__ void pack_ea_kernel(const float* __restrict__ ea) {
    int e = blockIdx.x * blockDim.x + threadIdx.x;
    if (e < N_EDGES) {
        float4 a = *reinterpret_cast<const float4*>(ea + (size_t)e * 4);
        uint4* p = reinterpret_cast<uint4*>(g_eap + (size_t)e * 8);
        p[0] = make_uint4(packh2(a.x, a.y), packh2(a.z, a.w), 0u, 0u);
        p[1] = make_uint4(0u, 0u, 0u, 0u);
    }
}

// h = relu(x @ W + b); also writes packed fp16 hi/lo planes to g_hp
__global__ void lin_in_kernel(const float* __restrict__ x,
                              const float* __restrict__ W,
                              const float* __restrict__ b) {
    __shared__ float sx[IN_F];
    __shared__ float sh[H];
    int n = blockIdx.x;
    if (threadIdx.x < IN_F) sx[threadIdx.x] = x[(size_t)n * IN_F + threadIdx.x];
    __syncthreads();
    int c = threadIdx.x;
    float acc = __ldg(&b[c]);
#pragma unroll
    for (int k = 0; k < IN_F; k++)
        acc = fmaf(sx[k], __ldg(&W[k * H + c]), acc);
    float v = fmaxf(acc, 0.f);
    g_h[(size_t)n * H + c] = v;
    sh[c] = v;
    __syncthreads();
    if (threadIdx.x < 64) {
        int w = threadIdx.x;
        uint32_t hi, lo;
        hilo2h(sh[2 * w], sh[2 * w + 1], hi, lo);
        g_hp[(size_t)n * 128 + w]      = hi;
        g_hp[(size_t)n * 128 + 64 + w] = lo;
    }
}

// stage W[k][n] fp32 transposed into WT[n][k] single fp16 plane, stride pad
__device__ __forceinline__ void stage_w_f16(char* smem, const float* __restrict__ W,
                                            int off, int kdim, int pad) {
    for (int idx = threadIdx.x; idx < kdim * H; idx += blockDim.x) {
        int k = idx >> 7, n = idx & 127;
        *reinterpret_cast<__half*>(smem + off + (n * pad + k) * 2) = __float2half(W[idx]);
    }
}

// ======================= edge kernel =======================================
// 256 thr = 2 groups x 4 warps; 64-edge tiles per group, double-buffered A
// (single fp16 plane) via cp.async. ea folded as k=128..143; GEMM1 has 9
// uniform k-steps, GEMM2 has 8. Single-pass fp16.

__device__ __forceinline__ void edge_prefetch(
    uint32_t sb, int gb, int e0, int srcval, int ltid,
    const int* __restrict__ dst) {
    const int r  = ltid >> 1;
    const int hc = (ltid & 1) * 64;
    const uint32_t* sp = g_hp + (size_t)srcval * 128 + (hc >> 1);
    uint32_t dh = sb + SM_A + (uint32_t)gb * (uint32_t)A_BUF +
                  (uint32_t)(r * EPAD + hc) * 2u;
#pragma unroll
    for (int p = 0; p < 8; p++) CP_ASYNC16(dh + 16u * p, sp + 4 * p);
    if (ltid < 64) {
        const int e = e0 + ltid;
        uint32_t de = sb + SM_A + (uint32_t)gb * (uint32_t)A_BUF +
                      (uint32_t)(ltid * EPAD + 128) * 2u;
        const uint32_t* ep = g_eap + (size_t)e * 8;
        CP_ASYNC16(de, ep);
        CP_ASYNC16(de + 16u, ep + 4);
        CP_ASYNC4(sb + SM_DST + (uint32_t)gb * 256u + (uint32_t)ltid * 4u, dst + e);
    }
}

__global__ void __launch_bounds__(256, 1)
edge_kernel(const int* __restrict__ src, const int* __restrict__ dst,
            const float* __restrict__ W1, const float* __restrict__ b1,
            const float* __restrict__ W2, const float* __restrict__ b2) {
    extern __shared__ char smem[];
    const uint32_t sb = smem_u32(smem);
    float* s_b1 = reinterpret_cast<float*>(smem + SM_B1);
    float* s_b2 = reinterpret_cast<float*>(smem + SM_B2);

    const int tid  = threadIdx.x;
    const int wid  = tid >> 5;
    const int lane = tid & 31;
    const int g    = wid >> 2;
    const int lw   = wid & 3;
    const int ltid = tid & 127;

    // W1 tile: k=0..127 main, k=128..131 = ea rows, 132..143 zero
    for (int idx = tid; idx < 144 * 128; idx += 256) {
        int k = idx >> 7, n = idx & 127;
        float v = (k < 128) ? W1[k * H + n]
                : (k < 132) ? W1[(H + k - 128) * H + n] : 0.f;
        *reinterpret_cast<__half*>(smem + SM_W1 + (n * EPAD + k) * 2) = __float2half(v);
    }
    for (int idx = tid; idx < 128 * 128; idx += 256) {
        int k = idx >> 7, n = idx & 127;
        *reinterpret_cast<__half*>(smem + SM_W2 + (n * EPAD + k) * 2) =
            __float2half(W2[idx]);
    }
    if (tid < 128) {
        s_b1[tid] = b1[tid];
        s_b2[tid] = b2[tid];
    }
    __syncthreads();

    const int m0 = lw * 16;
    const int rq = lane >> 2;
    const int cp = (lane & 3) * 2;
    const uint32_t aOffLane = ((uint32_t)(m0 + (lane & 15)) * EPAD + 8u * (lane >> 4)) * 2u;
    const uint32_t bOffLane = ((uint32_t)((lane & 7) + 8 * ((lane >> 3) & 1)) * EPAD +
                               8u * (lane >> 4)) * 2u;

    const int NT = N_EDGES / 64;  // 9375
    const int stride = gridDim.x * 2;
    int t = blockIdx.x * 2 + g;
    int buf = 0;
    int nsrc = 0;

    if (t < NT) {
        nsrc = __ldg(&src[t * 64 + (ltid >> 1)]);
        edge_prefetch(sb, g * 2, t * 64, nsrc, ltid, dst);
        CP_COMMIT();
        int t2 = t + stride;
        nsrc = (t2 < NT) ? __ldg(&src[t2 * 64 + (ltid >> 1)]) : 0;
    }

    for (; t < NT; t += stride) {
        CP_WAIT0();
        GROUP_BAR(g);

        const int tn = t + stride;
        if (tn < NT) {
            edge_prefetch(sb, g * 2 + (buf ^ 1), tn * 64, nsrc, ltid, dst);
            CP_COMMIT();
            const int tnn = tn + stride;
            if (tnn < NT) nsrc = __ldg(&src[tnn * 64 + (ltid >> 1)]);
        }

        const uint32_t bA = sb + SM_A + (uint32_t)(g * 2 + buf) * (uint32_t)A_BUF;
        int* s_dst = reinterpret_cast<int*>(smem + SM_DST + (g * 2 + buf) * 256);

        // ---- acc init = b1 (ea term comes from MMA k-step 8)
        float acc[16][4];
#pragma unroll
        for (int j = 0; j < 16; j++) {
            const int n = j * 8 + cp;
            acc[j][0] = s_b1[n]; acc[j][1] = s_b1[n + 1];
            acc[j][2] = s_b1[n]; acc[j][3] = s_b1[n + 1];
        }

        // ---- GEMM1: 9 uniform k-steps (k=128..143 = ea @ W1b)
#pragma unroll
        for (int ks = 0; ks < 9; ks++) {
            const uint32_t k0b = (uint32_t)ks * 32u;
            uint32_t ah[4];
            ldsm_x4(ah, bA + aOffLane + k0b);
#pragma unroll
            for (int jj = 0; jj < 8; jj++) {
                const uint32_t bo = bOffLane + k0b + (uint32_t)jj * (16 * EPAD * 2);
                uint32_t bh[4];
                ldsm_x4(bh, sb + SM_W1 + bo);
                mma16816(acc[2 * jj],     ah, bh[0], bh[2]);
                mma16816(acc[2 * jj + 1], ah, bh[1], bh[3]);
            }
        }

        // ---- relu + single-plane fp16 re-pack (C frags -> A frags)
        uint32_t a2[8][4];
#pragma unroll
        for (int gg = 0; gg < 8; gg++) {
            a2[gg][0] = packh2(fmaxf(acc[2 * gg][0], 0.f),     fmaxf(acc[2 * gg][1], 0.f));
            a2[gg][1] = packh2(fmaxf(acc[2 * gg][2], 0.f),     fmaxf(acc[2 * gg][3], 0.f));
            a2[gg][2] = packh2(fmaxf(acc[2 * gg + 1][0], 0.f), fmaxf(acc[2 * gg + 1][1], 0.f));
            a2[gg][3] = packh2(fmaxf(acc[2 * gg + 1][2], 0.f), fmaxf(acc[2 * gg + 1][3], 0.f));
        }

#pragma unroll
        for (int j = 0; j < 16; j++) {
            const int n = j * 8 + cp;
            acc[j][0] = s_b2[n]; acc[j][1] = s_b2[n + 1];
            acc[j][2] = s_b2[n]; acc[j][3] = s_b2[n + 1];
        }

        // ---- GEMM2 (single pass)
#pragma unroll
        for (int ks = 0; ks < 8; ks++) {
            const uint32_t k0b = (uint32_t)ks * 32u;
#pragma unroll
            for (int jj = 0; jj < 8; jj++) {
                const uint32_t bo = bOffLane + k0b + (uint32_t)jj * (16 * EPAD * 2);
                uint32_t bh[4];
                ldsm_x4(bh, sb + SM_W2 + bo);
                mma16816(acc[2 * jj],     a2[ks], bh[0], bh[2]);
                mma16816(acc[2 * jj + 1], a2[ks], bh[1], bh[3]);
            }
        }

        // ---- relu + float2 atomic scatter
        {
            const int r0 = m0 + rq, r1 = r0 + 8;
            float* p0 = g_agg + (size_t)s_dst[r0] * H;
            float* p1 = g_agg + (size_t)s_dst[r1] * H;
#pragma unroll
            for (int j = 0; j < 16; j++) {
                const int n = j * 8 + cp;
                atomicAdd(reinterpret_cast<float2*>(p0 + n),
                          make_float2(fmaxf(acc[j][0], 0.f), fmaxf(acc[j][1], 0.f)));
                atomicAdd(reinterpret_cast<float2*>(p1 + n),
                          make_float2(fmaxf(acc[j][2], 0.f), fmaxf(acc[j][3], 0.f)));
            }
        }
        buf ^= 1;
    }
}

// ======================= node1: U = relu([h|agg/cnt]@W1 + b1) ==============
// fp16 2-pass; phase1 also ZEROES g_agg for the next layer.

__global__ void __launch_bounds__(256, 1)
node1_kernel(const float* __restrict__ W1, const float* __restrict__ b1) {
    extern __shared__ char smem[];
    const uint32_t sb = smem_u32(smem);
    float* s_b1 = reinterpret_cast<float*>(smem + N1_B1);

    const int tid  = threadIdx.x;
    const int wid  = tid >> 5;
    const int lane = tid & 31;

    stage_w_f16(smem, W1, N1_W1, 2 * H, PADW);
    if (tid < 128) s_b1[tid] = b1[tid];
    __syncthreads();

    const int m0 = wid * 16;
    const int rq = lane >> 2;
    const int cp = (lane & 3) * 2;
    const uint32_t aOffLane = ((uint32_t)(m0 + (lane & 15)) * PAD + 8u * (lane >> 4)) * 2u;
    const uint32_t bOffLane = ((uint32_t)((lane & 7) + 8 * ((lane >> 3) & 1)) * PADW +
                               8u * (lane >> 4)) * 2u;

    const int NTN = (N_NODES + 127) / 128;

    for (int t = blockIdx.x; t < NTN; t += gridDim.x) {
        float acc[16][4];
#pragma unroll
        for (int j = 0; j < 16; j++) {
            const int n = j * 8 + cp;
            acc[j][0] = s_b1[n]; acc[j][1] = s_b1[n + 1];
            acc[j][2] = s_b1[n]; acc[j][3] = s_b1[n + 1];
        }

#pragma unroll 1
        for (int phase = 0; phase < 2; phase++) {
            if (phase == 0) {
                for (int i = tid; i < 128 * 64; i += 256) {
                    const int r = i >> 6, w = i & 63;
                    const int node = t * 128 + r;
                    uint32_t hi = 0, lo = 0;
                    if (node < N_NODES) {
                        hi = g_hp[(size_t)node * 128 + w];
                        lo = g_hp[(size_t)node * 128 + 64 + w];
                    }
                    const int o = (r * PAD + 2 * w) * 2;
                    *reinterpret_cast<uint32_t*>(smem + N1_AH + o) = hi;
                    *reinterpret_cast<uint32_t*>(smem + N1_AL + o) = lo;
                }
            } else {
                const int r = tid >> 1;
                const int hc = (tid & 1) * 64;
                const int node = t * 128 + r;
                const bool v = (node < N_NODES);
                const float* hp = g_agg + (size_t)(v ? node : 0) * H + hc;
                const float sc = v ? __ldg(&g_inv[node]) : 0.f;
                char* dh = smem + N1_AH + (r * PAD + hc) * 2;
                char* dl = smem + N1_AL + (r * PAD + hc) * 2;
#pragma unroll
                for (int p = 0; p < 8; p++) {
                    float4 v0 = v ? *reinterpret_cast<const float4*>(hp + 8 * p)
                                  : make_float4(0.f, 0.f, 0.f, 0.f);
                    float4 v1 = v ? *reinterpret_cast<const float4*>(hp + 8 * p + 4)
                                  : make_float4(0.f, 0.f, 0.f, 0.f);
                    uint4 wh, wl;
                    hilo2h(v0.x * sc, v0.y * sc, wh.x, wl.x);
                    hilo2h(v0.z * sc, v0.w * sc, wh.y, wl.y);
                    hilo2h(v1.x * sc, v1.y * sc, wh.z, wl.z);
                    hilo2h(v1.z * sc, v1.w * sc, wh.w, wl.w);
                    *reinterpret_cast<uint4*>(dh + p * 16) = wh;
                    *reinterpret_cast<uint4*>(dl + p * 16) = wl;
                }
                // zero g_agg for the next layer (each row touched exactly once)
                if (v) {
                    float4 z = make_float4(0.f, 0.f, 0.f, 0.f);
                    float* zp = g_agg + (size_t)node * H + hc;
#pragma unroll
                    for (int p = 0; p < 16; p++)
                        reinterpret_cast<float4*>(zp)[p] = z;
                }
            }
            __syncthreads();

            const uint32_t kbase = (uint32_t)(phase * 128) * 2u;
#pragma unroll
            for (int ks = 0; ks < 8; ks++) {
                const uint32_t k0a = (uint32_t)(ks * 16) * 2u;
                const uint32_t k0b = kbase + k0a;
                uint32_t ah[4], al[4];
                ldsm_x4(ah, sb + N1_AH + aOffLane + k0a);
                ldsm_x4(al, sb + N1_AL + aOffLane + k0a);
#pragma unroll
                for (int jj = 0; jj < 8; jj++) {
                    const uint32_t bo = bOffLane + k0b + (uint32_t)jj * (16 * PADW * 2);
                    uint32_t bh[4];
                    ldsm_x4(bh, sb + N1_W1 + bo);
                    mma16816(acc[2 * jj],     ah, bh[0], bh[2]);
                    mma16816(acc[2 * jj + 1], ah, bh[1], bh[3]);
                    mma16816(acc[2 * jj],     al, bh[0], bh[2]);
                    mma16816(acc[2 * jj + 1], al, bh[1], bh[3]);
                }
            }
            __syncthreads();
        }

        // epilogue: relu -> packed fp16 hi/lo -> g_u
        {
            const int r0 = m0 + rq, r1 = r0 + 8;
            const int n0 = t * 128 + r0, n1 = t * 128 + r1;
            const int wq = lane & 3;
#pragma unroll
            for (int j = 0; j < 16; j++) {
                const int w = j * 4 + wq;
                uint32_t hi0, lo0, hi1, lo1;
                hilo2h(fmaxf(acc[j][0], 0.f), fmaxf(acc[j][1], 0.f), hi0, lo0);
                hilo2h(fmaxf(acc[j][2], 0.f), fmaxf(acc[j][3], 0.f), hi1, lo1);
                if (n0 < N_NODES) {
                    g_u[(size_t)n0 * 128 + w]      = hi0;
                    g_u[(size_t)n0 * 128 + 64 + w] = lo0;
                }
                if (n1 < N_NODES) {
                    g_u[(size_t)n1 * 128 + w]      = hi1;
                    g_u[(size_t)n1 * 128 + 64 + w] = lo1;
                }
            }
        }
    }
}

// ======================= node2: h = relu(U@W2 + b2 + h) ====================

__global__ void __launch_bounds__(256, 1)
node2_kernel(const float* __restrict__ W2, const float* __restrict__ b2) {
    extern __shared__ char smem[];
    const uint32_t sb = smem_u32(smem);
    float* s_b2 = reinterpret_cast<float*>(smem + N2_B2);

    const int tid  = threadIdx.x;
    const int wid  = tid >> 5;
    const int lane = tid & 31;

    stage_w_f16(smem, W2, N2_W2, H, PAD);
    if (tid < 128) s_b2[tid] = b2[tid];
    __syncthreads();

    const int m0 = wid * 16;
    const int rq = lane >> 2;
    const int cp = (lane & 3) * 2;
    const uint32_t aOffLane = ((uint32_t)(m0 + (lane & 15)) * PAD + 8u * (lane >> 4)) * 2u;
    const uint32_t bOffLane = ((uint32_t)((lane & 7) + 8 * ((lane >> 3) & 1)) * PAD +
                               8u * (lane >> 4)) * 2u;

    const int NTN = (N_NODES + 127) / 128;

    for (int t = blockIdx.x; t < NTN; t += gridDim.x) {
        for (int i = tid; i < 128 * 64; i += 256) {
            const int r = i >> 6, w = i & 63;
            const int node = t * 128 + r;
            uint32_t hi = 0, lo = 0;
            if (node < N_NODES) {
                hi = g_u[(size_t)node * 128 + w];
                lo = g_u[(size_t)node * 128 + 64 + w];
            }
            const int o = (r * PAD + 2 * w) * 2;
            *reinterpret_cast<uint32_t*>(smem + N2_AH + o) = hi;
            *reinterpret_cast<uint32_t*>(smem + N2_AL + o) = lo;
        }
        __syncthreads();

        float acc[16][4];
#pragma unroll
        for (int j = 0; j < 16; j++) {
            const int n = j * 8 + cp;
            acc[j][0] = s_b2[n]; acc[j][1] = s_b2[n + 1];
            acc[j][2] = s_b2[n]; acc[j][3] = s_b2[n + 1];
        }

#pragma unroll
        for (int ks = 0; ks < 8; ks++) {
            const uint32_t k0b = (uint32_t)(ks * 16) * 2u;
            uint32_t ah[4], al[4];
            ldsm_x4(ah, sb + N2_AH + aOffLane + k0b);
            ldsm_x4(al, sb + N2_AL + aOffLane + k0b);
#pragma unroll
            for (int jj = 0; jj < 8; jj++) {
                const uint32_t bo = bOffLane + k0b + (uint32_t)jj * (16 * PAD * 2);
                uint32_t bh[4];
                ldsm_x4(bh, sb + N2_W2 + bo);
                mma16816(acc[2 * jj],     ah, bh[0], bh[2]);
                mma16816(acc[2 * jj + 1], ah, bh[1], bh[3]);
                mma16816(acc[2 * jj],     al, bh[0], bh[2]);
                mma16816(acc[2 * jj + 1], al, bh[1], bh[3]);
            }
        }

        // epilogue: + h residual, relu, write g_h fp32 + packed g_hp
        {
            const int r0 = m0 + rq, r1 = r0 + 8;
            const int n0 = t * 128 + r0, n1 = t * 128 + r1;
#pragma unroll
            for (int j = 0; j < 16; j++) {
                const int n = j * 8 + cp;
                const int w = n >> 1;
                if (n0 < N_NODES) {
                    float2 h0 = *reinterpret_cast<const float2*>(g_h + (size_t)n0 * H + n);
                    float2 o0 = make_float2(fmaxf(acc[j][0] + h0.x, 0.f),
                                            fmaxf(acc[j][1] + h0.y, 0.f));
                    *reinterpret_cast<float2*>(g_h + (size_t)n0 * H + n) = o0;
                    uint32_t hi, lo;
                    hilo2h(o0.x, o0.y, hi, lo);
                    g_hp[(size_t)n0 * 128 + w]      = hi;
                    g_hp[(size_t)n0 * 128 + 64 + w] = lo;
                }
                if (n1 < N_NODES) {
                    float2 h1 = *reinterpret_cast<const float2*>(g_h + (size_t)n1 * H + n);
                    float2 o1 = make_float2(fmaxf(acc[j][2] + h1.x, 0.f),
                                            fmaxf(acc[j][3] + h1.y, 0.f));
                    *reinterpret_cast<float2*>(g_h + (size_t)n1 * H + n) = o1;
                    uint32_t hi, lo;
                    hilo2h(o1.x, o1.y, hi, lo);
                    g_hp[(size_t)n1 * 128 + w]      = hi;
                    g_hp[(size_t)n1 * 128 + 64 + w] = lo;
                }
            }
        }
        __syncthreads();
    }
}

// ======================= head ==============================================

__global__ void __launch_bounds__(256, 1)
head_kernel(const float* __restrict__ W1, const float* __restrict__ b1,
            const float* __restrict__ W2, const float* __restrict__ b2,
            float* __restrict__ out) {
    extern __shared__ float sm[];
    float* sW1 = sm;
    float* sW2 = sW1 + H * H;
    float* sH  = sW2 + H * N_OUT;

    for (int i = threadIdx.x; i < H * H; i += 256) sW1[i] = W1[i];
    for (int i = threadIdx.x; i < H * N_OUT; i += 256) sW2[i] = W2[i];

    const int lane = threadIdx.x & 31;
    const int w    = threadIdx.x >> 5;
    float b1v[4];
#pragma unroll
    for (int j = 0; j < 4; j++) b1v[j] = __ldg(&b1[lane * 4 + j]);
    const float b2v0 = __ldg(&b2[0]), b2v1 = __ldg(&b2[1]), b2v2 = __ldg(&b2[2]);
    __syncthreads();

    const int ntiles = (N_NODES + TN - 1) / TN;
    for (int t = blockIdx.x; t < ntiles; t += gridDim.x) {
        const int n0 = t * TN + w * 4;
#pragma unroll
        for (int i = 0; i < 4; i++) {
            int n = n0 + i;
            float4 hv = make_float4(0.f, 0.f, 0.f, 0.f);
            if (n < N_NODES)
                hv = *reinterpret_cast<const float4*>(g_h + (size_t)n * H + lane * 4);
            *reinterpret_cast<float4*>(sH + (w * 4 + i) * H + lane * 4) = hv;
        }
        __syncwarp();

        float acc[4][4];
#pragma unroll
        for (int i = 0; i < 4; i++) {
            acc[i][0] = b1v[0]; acc[i][1] = b1v[1];
            acc[i][2] = b1v[2]; acc[i][3] = b1v[3];
        }
#pragma unroll 1
        for (int kc = 0; kc < H; kc += 4) {
            float4 a4[4];
#pragma unroll
            for (int i = 0; i < 4; i++)
                a4[i] = *reinterpret_cast<const float4*>(sH + (w * 4 + i) * H + kc);
#pragma unroll
            for (int kk = 0; kk < 4; kk++) {
                float4 bv = *reinterpret_cast<const float4*>(sW1 + (kc + kk) * H + lane * 4);
#pragma unroll
                for (int i = 0; i < 4; i++) {
                    float a = (kk == 0) ? a4[i].x : (kk == 1) ? a4[i].y
                             : (kk == 2) ? a4[i].z : a4[i].w;
                    acc[i][0] = fmaf(a, bv.x, acc[i][0]);
                    acc[i][1] = fmaf(a, bv.y, acc[i][1]);
                    acc[i][2] = fmaf(a, bv.z, acc[i][2]);
                    acc[i][3] = fmaf(a, bv.w, acc[i][3]);
                }
            }
        }

#pragma unroll
        for (int i = 0; i < 4; i++) {
            float p0 = 0.f, p1 = 0.f, p2 = 0.f;
#pragma unroll
            for (int j = 0; j < 4; j++) {
                float o = fmaxf(acc[i][j], 0.f);
                int kk = lane * 4 + j;
                p0 = fmaf(o, sW2[kk * N_OUT + 0], p0);
                p1 = fmaf(o, sW2[kk * N_OUT + 1], p1);
                p2 = fmaf(o, sW2[kk * N_OUT + 2], p2);
            }
#pragma unroll
            for (int off = 16; off > 0; off >>= 1) {
                p0 += __shfl_xor_sync(0xffffffffu, p0, off);
                p1 += __shfl_xor_sync(0xffffffffu, p1, off);
                p2 += __shfl_xor_sync(0xffffffffu, p2, off);
            }
            int n = n0 + i;
            if (lane == 0 && n < N_NODES) {
                out[(size_t)n * N_OUT + 0] = fmaxf(p0 + b2v0, 0.f);
                out[(size_t)n * N_OUT + 1] = fmaxf(p1 + b2v1, 0.f);
                out[(size_t)n * N_OUT + 2] = fmaxf(p2 + b2v2, 0.f);
            }
        }
        __syncwarp();
    }
}

// ======================= launch ============================================

extern "C" void kernel_launch(void* const* d_in, const int* in_sizes, int n_in,
                              void* d_out, int out_size) {
    const float* x       = (const float*)d_in[0];
    const int*   ei      = (const int*)d_in[1];
    const float* ea      = (const float*)d_in[2];
    const float* lin_w   = (const float*)d_in[3];
    const float* lin_b   = (const float*)d_in[4];
    const float* msg_w1  = (const float*)d_in[5];
    const float* msg_b1  = (const float*)d_in[6];
    const float* msg_w2  = (const float*)d_in[7];
    const float* msg_b2  = (const float*)d_in[8];
    const float* upd_w1  = (const float*)d_in[9];
    const float* upd_b1  = (const float*)d_in[10];
    const float* upd_w2  = (const float*)d_in[11];
    const float* upd_b2  = (const float*)d_in[12];
    const float* head_w1 = (const float*)d_in[13];
    const float* head_b1 = (const float*)d_in[14];
    const float* head_w2 = (const float*)d_in[15];
    const float* head_b2 = (const float*)d_in[16];
    float* out = (float*)d_out;

    const int* src = ei;
    const int* dst = ei + N_EDGES;

    int sm_count = 148;
    cudaDeviceGetAttribute(&sm_count, cudaDevAttrMultiProcessorCount, 0);

    const size_t smHd = (size_t)(H * H + H * N_OUT + TN * H) * sizeof(float);
    cudaFuncSetAttribute(edge_kernel, cudaFuncAttributeMaxDynamicSharedMemorySize, SM_EDGE_TOTAL);
    cudaFuncSetAttribute(node1_kernel, cudaFuncAttributeMaxDynamicSharedMemorySize, N1_TOTAL);
    cudaFuncSetAttribute(node2_kernel, cudaFuncAttributeMaxDynamicSharedMemorySize, N2_TOTAL);
    cudaFuncSetAttribute(head_kernel, cudaFuncAttributeMaxDynamicSharedMemorySize, (int)smHd);

    zero_cnt_kernel<<<(N_NODES + 255) / 256, 256>>>();
    deg_kernel<<<(N_EDGES + 255) / 256, 256>>>(dst);
    inv_kernel<<<(N_NODES + 255) / 256, 256>>>();
    lin_in_kernel<<<N_NODES, H>>>(x, lin_w, lin_b);
    pack_ea_kernel<<<(N_EDGES + 255) / 256, 256>>>(ea);
    zero_agg_kernel<<<1024, 256>>>();   // layer 0 only; node1 zeroes thereafter

    for (int l = 0; l < N_LAYERS; l++) {
        edge_kernel<<<sm_count, 256, SM_EDGE_TOTAL>>>(
            src, dst,
            msg_w1 + (size_t)l * (H + ED) * H, msg_b1 + (size_t)l * H,
            msg_w2 + (size_t)l * H * H, msg_b2 + (size_t)l * H);
        node1_kernel<<<sm_count, 256, N1_TOTAL>>>(
            upd_w1 + (size_t)l * 2 * H * H, upd_b1 + (size_t)l * H);
        node2_kernel<<<sm_count, 256, N2_TOTAL>>>(
            upd_w2 + (size_t)l * H * H, upd_b2 + (size_t)l * H);
    }

    head_kernel<<<2 * sm_count, 256, smHd>>>(head_w1, head_b1, head_w2, head_b2, out);
}

// round 10
// speedup vs baseline: 3.3552x; 1.1471x over previous
#include <cuda_runtime.h>
#include <cuda_fp16.h>
#include <cstdint>
#include <cstddef>

// ---------------------------------------------------------------------------
// MeshGNN: N=50000, E=600000, IN=16, ED=4, H=128, L=4, OUT=3
// Round 9 (= Round 8 resubmit; prior bench was an infra failure):
// fused single-pass fp16 node kernel (GEMM1 K=256 -> register relu/re-pack ->
// GEMM2 -> residual), g_u eliminated, g_hp compacted to hi-plane only.
// Edge kernel: single-pass fp16, ea folded as k=128..143, cp.async
// double-buffered, dual-group pipelined.
// ---------------------------------------------------------------------------

#define N_NODES 50000
#define N_EDGES 600000
#define H 128
#define IN_F 16
#define ED 4
#define N_LAYERS 4
#define N_OUT 3
#define TN 32

#define PAD  136   // node A / W2 k stride (elements)
#define PADW 264   // node W1 (K=256) stride
#define EPAD 152   // edge kernel stride: 128 ch + 16 ea block + 8 slack

#define A_BUF  19456   // 64 * EPAD * 2

// ---- edge kernel smem map (bytes)
#define SM_B1   0
#define SM_B2   512
#define SM_DST  1024     // + (g*2+b)*256
#define SM_W1   4096     // 38912 (incl. ea rows at k=128..143)
#define SM_W2   43008    // 38912
#define SM_A    81920    // + (g*2+b)*19456
#define SM_EDGE_TOTAL 159744

// ---- fused node smem map
#define NB_B    0        // b1[128] b2[128] = 1024
#define NB_W1   1024     // 128*PADW*2 = 67584
#define NB_W2   68608    // 128*PAD*2  = 34816
#define NB_A    103424   // 128*PAD*2  = 34816
#define NB_TOTAL 138240

__device__ float g_h[(size_t)N_NODES * H];
__device__ float g_agg[(size_t)N_NODES * H];
__device__ float g_inv[N_NODES];
__device__ uint32_t g_hp[(size_t)N_NODES * 64];    // packed fp16 h (hi plane only)
__device__ uint32_t g_eap[(size_t)N_EDGES * 8];    // fp16 ea block (4 real + 12 zero)

// ======================= helpers ==========================================

__device__ __forceinline__ uint32_t smem_u32(const void* p) {
    uint32_t a;
    asm("{ .reg .u64 t; cvta.to.shared.u64 t, %1; cvt.u32.u64 %0, t; }"
        : "=r"(a) : "l"(p));
    return a;
}

__device__ __forceinline__ void ldsm_x4(uint32_t* r, uint32_t addr) {
    asm volatile("ldmatrix.sync.aligned.m8n8.x4.shared.b16 {%0,%1,%2,%3}, [%4];"
                 : "=r"(r[0]), "=r"(r[1]), "=r"(r[2]), "=r"(r[3]) : "r"(addr));
}

__device__ __forceinline__ void mma16816(float* c, const uint32_t* a,
                                         uint32_t b0, uint32_t b1) {
    asm volatile(
        "mma.sync.aligned.m16n8k16.row.col.f32.f16.f16.f32 "
        "{%0,%1,%2,%3}, {%4,%5,%6,%7}, {%8,%9}, {%0,%1,%2,%3};"
        : "+f"(c[0]), "+f"(c[1]), "+f"(c[2]), "+f"(c[3])
        : "r"(a[0]), "r"(a[1]), "r"(a[2]), "r"(a[3]), "r"(b0), "r"(b1));
}

__device__ __forceinline__ uint32_t packh2(float x, float y) {
    __half2 h = __floats2half2_rn(x, y);
    return *reinterpret_cast<uint32_t*>(&h);
}

#define GROUP_BAR(gid) \
    asm volatile("bar.sync %0, %1;" :: "r"(1 + (gid)), "r"(128) : "memory")

#define CP_ASYNC16(dst, src) \
    asm volatile("cp.async.ca.shared.global [%0], [%1], 16;" :: "r"(dst), "l"(src) : "memory")
#define CP_ASYNC4(dst, src) \
    asm volatile("cp.async.ca.shared.global [%0], [%1], 4;" :: "r"(dst), "l"(src) : "memory")
#define CP_COMMIT() asm volatile("cp.async.commit_group;" ::: "memory")
#define CP_WAIT0()  asm volatile("cp.async.wait_group 0;" ::: "memory")

// ======================= small helper kernels ==============================

__global__ void zero_agg_kernel() {
    size_t i = (size_t)blockIdx.x * blockDim.x + threadIdx.x;
    const size_t n4 = (size_t)N_NODES * H / 4;
    float4 z = make_float4(0.f, 0.f, 0.f, 0.f);
    for (; i < n4; i += (size_t)gridDim.x * blockDim.x)
        reinterpret_cast<float4*>(g_agg)[i] = z;
}

__global__ void zero_cnt_kernel() {
    int i = blockIdx.x * blockDim.x + threadIdx.x;
    if (i < N_NODES) g_inv[i] = 0.f;
}

__global__ void deg_kernel(const int* __restrict__ dst) {
    int e = blockIdx.x * blockDim.x + threadIdx.x;
    if (e < N_EDGES) atomicAdd(&g_inv[dst[e]], 1.0f);
}

__global__ void inv_kernel() {
    int i = blockIdx.x * blockDim.x + threadIdx.x;
    if (i < N_NODES) g_inv[i] = 1.0f / fmaxf(g_inv[i], 1.0f);
}

__global__ void pack_ea_kernel(const float* __restrict__ ea) {
    int e = blockIdx.x * blockDim.x + threadIdx.x;
    if (e < N_EDGES) {
        float4 a = *reinterpret_cast<const float4*>(ea + (size_t)e * 4);
        uint4* p = reinterpret_cast<uint4*>(g_eap + (size_t)e * 8);
        p[0] = make_uint4(packh2(a.x, a.y), packh2(a.z, a.w), 0u, 0u);
        p[1] = make_uint4(0u, 0u, 0u, 0u);
    }
}

// h = relu(x @ W + b); writes fp32 g_h + packed fp16 hi plane g_hp
__global__ void lin_in_kernel(const float* __restrict__ x,
                              const float* __restrict__ W,
                              const float* __restrict__ b) {
    __shared__ float sx[IN_F];
    __shared__ float sh[H];
    int n = blockIdx.x;
    if (threadIdx.x < IN_F) sx[threadIdx.x] = x[(size_t)n * IN_F + threadIdx.x];
    __syncthreads();
    int c = threadIdx.x;
    float acc = __ldg(&b[c]);
#pragma unroll
    for (int k = 0; k < IN_F; k++)
        acc = fmaf(sx[k], __ldg(&W[k * H + c]), acc);
    float v = fmaxf(acc, 0.f);
    g_h[(size_t)n * H + c] = v;
    sh[c] = v;
    __syncthreads();
    if (threadIdx.x < 64) {
        int w = threadIdx.x;
        g_hp[(size_t)n * 64 + w] = packh2(sh[2 * w], sh[2 * w + 1]);
    }
}

// stage W[k][n] fp32 transposed into WT[n][k] fp16, stride pad
__device__ __forceinline__ void stage_w_f16(char* smem, const float* __restrict__ W,
                                            int off, int kdim, int pad) {
    for (int idx = threadIdx.x; idx < kdim * H; idx += blockDim.x) {
        int k = idx >> 7, n = idx & 127;
        *reinterpret_cast<__half*>(smem + off + (n * pad + k) * 2) = __float2half(W[idx]);
    }
}

// ======================= edge kernel =======================================
// 256 thr = 2 groups x 4 warps; 64-edge tiles, double-buffered cp.async A,
// ea folded as k=128..143; single-pass fp16.

__device__ __forceinline__ void edge_prefetch(
    uint32_t sb, int gb, int e0, int srcval, int ltid,
    const int* __restrict__ dst) {
    const int r  = ltid >> 1;
    const int hc = (ltid & 1) * 64;
    const uint32_t* sp = g_hp + (size_t)srcval * 64 + (ltid & 1) * 32;
    uint32_t dh = sb + SM_A + (uint32_t)gb * (uint32_t)A_BUF +
                  (uint32_t)(r * EPAD + hc) * 2u;
#pragma unroll
    for (int p = 0; p < 8; p++) CP_ASYNC16(dh + 16u * p, sp + 4 * p);
    if (ltid < 64) {
        const int e = e0 + ltid;
        uint32_t de = sb + SM_A + (uint32_t)gb * (uint32_t)A_BUF +
                      (uint32_t)(ltid * EPAD + 128) * 2u;
        const uint32_t* ep = g_eap + (size_t)e * 8;
        CP_ASYNC16(de, ep);
        CP_ASYNC16(de + 16u, ep + 4);
        CP_ASYNC4(sb + SM_DST + (uint32_t)gb * 256u + (uint32_t)ltid * 4u, dst + e);
    }
}

__global__ void __launch_bounds__(256, 1)
edge_kernel(const int* __restrict__ src, const int* __restrict__ dst,
            const float* __restrict__ W1, const float* __restrict__ b1,
            const float* __restrict__ W2, const float* __restrict__ b2) {
    extern __shared__ char smem[];
    const uint32_t sb = smem_u32(smem);
    float* s_b1 = reinterpret_cast<float*>(smem + SM_B1);
    float* s_b2 = reinterpret_cast<float*>(smem + SM_B2);

    const int tid  = threadIdx.x;
    const int wid  = tid >> 5;
    const int lane = tid & 31;
    const int g    = wid >> 2;
    const int lw   = wid & 3;
    const int ltid = tid & 127;

    for (int idx = tid; idx < 144 * 128; idx += 256) {
        int k = idx >> 7, n = idx & 127;
        float v = (k < 128) ? W1[k * H + n]
                : (k < 132) ? W1[(H + k - 128) * H + n] : 0.f;
        *reinterpret_cast<__half*>(smem + SM_W1 + (n * EPAD + k) * 2) = __float2half(v);
    }
    for (int idx = tid; idx < 128 * 128; idx += 256) {
        int k = idx >> 7, n = idx & 127;
        *reinterpret_cast<__half*>(smem + SM_W2 + (n * EPAD + k) * 2) =
            __float2half(W2[idx]);
    }
    if (tid < 128) {
        s_b1[tid] = b1[tid];
        s_b2[tid] = b2[tid];
    }
    __syncthreads();

    const int m0 = lw * 16;
    const int rq = lane >> 2;
    const int cp = (lane & 3) * 2;
    const uint32_t aOffLane = ((uint32_t)(m0 + (lane & 15)) * EPAD + 8u * (lane >> 4)) * 2u;
    const uint32_t bOffLane = ((uint32_t)((lane & 7) + 8 * ((lane >> 3) & 1)) * EPAD +
                               8u * (lane >> 4)) * 2u;

    const int NT = N_EDGES / 64;  // 9375
    const int stride = gridDim.x * 2;
    int t = blockIdx.x * 2 + g;
    int buf = 0;
    int nsrc = 0;

    if (t < NT) {
        nsrc = __ldg(&src[t * 64 + (ltid >> 1)]);
        edge_prefetch(sb, g * 2, t * 64, nsrc, ltid, dst);
        CP_COMMIT();
        int t2 = t + stride;
        nsrc = (t2 < NT) ? __ldg(&src[t2 * 64 + (ltid >> 1)]) : 0;
    }

    for (; t < NT; t += stride) {
        CP_WAIT0();
        GROUP_BAR(g);

        const int tn = t + stride;
        if (tn < NT) {
            edge_prefetch(sb, g * 2 + (buf ^ 1), tn * 64, nsrc, ltid, dst);
            CP_COMMIT();
            const int tnn = tn + stride;
            if (tnn < NT) nsrc = __ldg(&src[tnn * 64 + (ltid >> 1)]);
        }

        const uint32_t bA = sb + SM_A + (uint32_t)(g * 2 + buf) * (uint32_t)A_BUF;
        int* s_dst = reinterpret_cast<int*>(smem + SM_DST + (g * 2 + buf) * 256);

        float acc[16][4];
#pragma unroll
        for (int j = 0; j < 16; j++) {
            const int n = j * 8 + cp;
            acc[j][0] = s_b1[n]; acc[j][1] = s_b1[n + 1];
            acc[j][2] = s_b1[n]; acc[j][3] = s_b1[n + 1];
        }

        // GEMM1: 9 uniform k-steps (k-step 8 = ea @ W1b)
#pragma unroll
        for (int ks = 0; ks < 9; ks++) {
            const uint32_t k0b = (uint32_t)ks * 32u;
            uint32_t ah[4];
            ldsm_x4(ah, bA + aOffLane + k0b);
#pragma unroll
            for (int jj = 0; jj < 8; jj++) {
                const uint32_t bo = bOffLane + k0b + (uint32_t)jj * (16 * EPAD * 2);
                uint32_t bh[4];
                ldsm_x4(bh, sb + SM_W1 + bo);
                mma16816(acc[2 * jj],     ah, bh[0], bh[2]);
                mma16816(acc[2 * jj + 1], ah, bh[1], bh[3]);
            }
        }

        // relu + fp16 re-pack (C frags -> A frags)
        uint32_t a2[8][4];
#pragma unroll
        for (int gg = 0; gg < 8; gg++) {
            a2[gg][0] = packh2(fmaxf(acc[2 * gg][0], 0.f),     fmaxf(acc[2 * gg][1], 0.f));
            a2[gg][1] = packh2(fmaxf(acc[2 * gg][2], 0.f),     fmaxf(acc[2 * gg][3], 0.f));
            a2[gg][2] = packh2(fmaxf(acc[2 * gg + 1][0], 0.f), fmaxf(acc[2 * gg + 1][1], 0.f));
            a2[gg][3] = packh2(fmaxf(acc[2 * gg + 1][2], 0.f), fmaxf(acc[2 * gg + 1][3], 0.f));
        }

#pragma unroll
        for (int j = 0; j < 16; j++) {
            const int n = j * 8 + cp;
            acc[j][0] = s_b2[n]; acc[j][1] = s_b2[n + 1];
            acc[j][2] = s_b2[n]; acc[j][3] = s_b2[n + 1];
        }

        // GEMM2
#pragma unroll
        for (int ks = 0; ks < 8; ks++) {
            const uint32_t k0b = (uint32_t)ks * 32u;
#pragma unroll
            for (int jj = 0; jj < 8; jj++) {
                const uint32_t bo = bOffLane + k0b + (uint32_t)jj * (16 * EPAD * 2);
                uint32_t bh[4];
                ldsm_x4(bh, sb + SM_W2 + bo);
                mma16816(acc[2 * jj],     a2[ks], bh[0], bh[2]);
                mma16816(acc[2 * jj + 1], a2[ks], bh[1], bh[3]);
            }
        }

        // relu + float2 atomic scatter
        {
            const int r0 = m0 + rq, r1 = r0 + 8;
            float* p0 = g_agg + (size_t)s_dst[r0] * H;
            float* p1 = g_agg + (size_t)s_dst[r1] * H;
#pragma unroll
            for (int j = 0; j < 16; j++) {
                const int n = j * 8 + cp;
                atomicAdd(reinterpret_cast<float2*>(p0 + n),
                          make_float2(fmaxf(acc[j][0], 0.f), fmaxf(acc[j][1], 0.f)));
                atomicAdd(reinterpret_cast<float2*>(p1 + n),
                          make_float2(fmaxf(acc[j][2], 0.f), fmaxf(acc[j][3], 0.f)));
            }
        }
        buf ^= 1;
    }
}

// ======================= fused node kernel =================================
// h = relu( relu([h | agg*inv] @ W1 + b1) @ W2 + b2 + h )
// Single-pass fp16; U lives only in registers (C-frag -> A-frag re-pack).
// Phase-1 staging also zeroes g_agg for the next layer.

__global__ void __launch_bounds__(256, 1)
node_kernel(const float* __restrict__ W1, const float* __restrict__ b1,
            const float* __restrict__ W2, const float* __restrict__ b2) {
    extern __shared__ char smem[];
    const uint32_t sb = smem_u32(smem);
    float* s_b1 = reinterpret_cast<float*>(smem + NB_B);
    float* s_b2 = s_b1 + 128;

    const int tid  = threadIdx.x;
    const int wid  = tid >> 5;
    const int lane = tid & 31;

    stage_w_f16(smem, W1, NB_W1, 2 * H, PADW);
    stage_w_f16(smem, W2, NB_W2, H, PAD);
    if (tid < 128) {
        s_b1[tid] = b1[tid];
        s_b2[tid] = b2[tid];
    }
    __syncthreads();

    const int m0 = wid * 16;
    const int rq = lane >> 2;
    const int cp = (lane & 3) * 2;
    const uint32_t aOffLane = ((uint32_t)(m0 + (lane & 15)) * PAD + 8u * (lane >> 4)) * 2u;
    const uint32_t b1OffLane = ((uint32_t)((lane & 7) + 8 * ((lane >> 3) & 1)) * PADW +
                                8u * (lane >> 4)) * 2u;
    const uint32_t b2OffLane = ((uint32_t)((lane & 7) + 8 * ((lane >> 3) & 1)) * PAD +
                                8u * (lane >> 4)) * 2u;

    const int NTN = (N_NODES + 127) / 128;  // 391

    for (int t = blockIdx.x; t < NTN; t += gridDim.x) {
        float acc[16][4];
#pragma unroll
        for (int j = 0; j < 16; j++) {
            const int n = j * 8 + cp;
            acc[j][0] = s_b1[n]; acc[j][1] = s_b1[n + 1];
            acc[j][2] = s_b1[n]; acc[j][3] = s_b1[n + 1];
        }

#pragma unroll 1
        for (int phase = 0; phase < 2; phase++) {
            if (phase == 0) {
                // A = h (copy packed fp16 from g_hp)
                for (int i = tid; i < 128 * 64; i += 256) {
                    const int r = i >> 6, w = i & 63;
                    const int node = t * 128 + r;
                    uint32_t hi = (node < N_NODES) ? g_hp[(size_t)node * 64 + w] : 0u;
                    *reinterpret_cast<uint32_t*>(smem + NB_A + (r * PAD + 2 * w) * 2) = hi;
                }
            } else {
                // A = agg * inv (fp32 -> fp16), then zero g_agg
                const int r = tid >> 1;
                const int hc = (tid & 1) * 64;
                const int node = t * 128 + r;
                const bool v = (node < N_NODES);
                const float* hp = g_agg + (size_t)(v ? node : 0) * H + hc;
                const float sc = v ? __ldg(&g_inv[node]) : 0.f;
                char* dh = smem + NB_A + (r * PAD + hc) * 2;
#pragma unroll
                for (int p = 0; p < 8; p++) {
                    float4 v0 = v ? *reinterpret_cast<const float4*>(hp + 8 * p)
                                  : make_float4(0.f, 0.f, 0.f, 0.f);
                    float4 v1 = v ? *reinterpret_cast<const float4*>(hp + 8 * p + 4)
                                  : make_float4(0.f, 0.f, 0.f, 0.f);
                    uint4 wh = make_uint4(packh2(v0.x * sc, v0.y * sc),
                                          packh2(v0.z * sc, v0.w * sc),
                                          packh2(v1.x * sc, v1.y * sc),
                                          packh2(v1.z * sc, v1.w * sc));
                    *reinterpret_cast<uint4*>(dh + p * 16) = wh;
                }
                if (v) {
                    float4 z = make_float4(0.f, 0.f, 0.f, 0.f);
                    float* zp = g_agg + (size_t)node * H + hc;
#pragma unroll
                    for (int p = 0; p < 16; p++)
                        reinterpret_cast<float4*>(zp)[p] = z;
                }
            }
            __syncthreads();

            const uint32_t kbase = (uint32_t)(phase * 128) * 2u;
#pragma unroll
            for (int ks = 0; ks < 8; ks++) {
                const uint32_t k0a = (uint32_t)ks * 32u;
                uint32_t ah[4];
                ldsm_x4(ah, sb + NB_A + aOffLane + k0a);
#pragma unroll
                for (int jj = 0; jj < 8; jj++) {
                    const uint32_t bo = b1OffLane + kbase + k0a +
                                        (uint32_t)jj * (16 * PADW * 2);
                    uint32_t bh[4];
                    ldsm_x4(bh, sb + NB_W1 + bo);
                    mma16816(acc[2 * jj],     ah, bh[0], bh[2]);
                    mma16816(acc[2 * jj + 1], ah, bh[1], bh[3]);
                }
            }
            __syncthreads();  // A consumed before next phase restages
        }

        // U = relu(acc) -> fp16 A-frags in registers
        uint32_t a2[8][4];
#pragma unroll
        for (int gg = 0; gg < 8; gg++) {
            a2[gg][0] = packh2(fmaxf(acc[2 * gg][0], 0.f),     fmaxf(acc[2 * gg][1], 0.f));
            a2[gg][1] = packh2(fmaxf(acc[2 * gg][2], 0.f),     fmaxf(acc[2 * gg][3], 0.f));
            a2[gg][2] = packh2(fmaxf(acc[2 * gg + 1][0], 0.f), fmaxf(acc[2 * gg + 1][1], 0.f));
            a2[gg][3] = packh2(fmaxf(acc[2 * gg + 1][2], 0.f), fmaxf(acc[2 * gg + 1][3], 0.f));
        }

#pragma unroll
        for (int j = 0; j < 16; j++) {
            const int n = j * 8 + cp;
            acc[j][0] = s_b2[n]; acc[j][1] = s_b2[n + 1];
            acc[j][2] = s_b2[n]; acc[j][3] = s_b2[n + 1];
        }

        // GEMM2: u2 = U @ W2 + b2
#pragma unroll
        for (int ks = 0; ks < 8; ks++) {
            const uint32_t k0b = (uint32_t)ks * 32u;
#pragma unroll
            for (int jj = 0; jj < 8; jj++) {
                const uint32_t bo = b2OffLane + k0b + (uint32_t)jj * (16 * PAD * 2);
                uint32_t bh[4];
                ldsm_x4(bh, sb + NB_W2 + bo);
                mma16816(acc[2 * jj],     a2[ks], bh[0], bh[2]);
                mma16816(acc[2 * jj + 1], a2[ks], bh[1], bh[3]);
            }
        }

        // epilogue: + h residual, relu, write g_h fp32 + g_hp hi plane
        {
            const int r0 = m0 + rq, r1 = r0 + 8;
            const int n0 = t * 128 + r0, n1 = t * 128 + r1;
#pragma unroll
            for (int j = 0; j < 16; j++) {
                const int n = j * 8 + cp;
                const int w = n >> 1;
                if (n0 < N_NODES) {
                    float2 h0 = *reinterpret_cast<const float2*>(g_h + (size_t)n0 * H + n);
                    float2 o0 = make_float2(fmaxf(acc[j][0] + h0.x, 0.f),
                                            fmaxf(acc[j][1] + h0.y, 0.f));
                    *reinterpret_cast<float2*>(g_h + (size_t)n0 * H + n) = o0;
                    g_hp[(size_t)n0 * 64 + w] = packh2(o0.x, o0.y);
                }
                if (n1 < N_NODES) {
                    float2 h1 = *reinterpret_cast<const float2*>(g_h + (size_t)n1 * H + n);
                    float2 o1 = make_float2(fmaxf(acc[j][2] + h1.x, 0.f),
                                            fmaxf(acc[j][3] + h1.y, 0.f));
                    *reinterpret_cast<float2*>(g_h + (size_t)n1 * H + n) = o1;
                    g_hp[(size_t)n1 * 64 + w] = packh2(o1.x, o1.y);
                }
            }
        }
        __syncthreads();
    }
}

// ======================= head ==============================================

__global__ void __launch_bounds__(256, 1)
head_kernel(const float* __restrict__ W1, const float* __restrict__ b1,
            const float* __restrict__ W2, const float* __restrict__ b2,
            float* __restrict__ out) {
    extern __shared__ float sm[];
    float* sW1 = sm;
    float* sW2 = sW1 + H * H;
    float* sH  = sW2 + H * N_OUT;

    for (int i = threadIdx.x; i < H * H; i += 256) sW1[i] = W1[i];
    for (int i = threadIdx.x; i < H * N_OUT; i += 256) sW2[i] = W2[i];

    const int lane = threadIdx.x & 31;
    const int w    = threadIdx.x >> 5;
    float b1v[4];
#pragma unroll
    for (int j = 0; j < 4; j++) b1v[j] = __ldg(&b1[lane * 4 + j]);
    const float b2v0 = __ldg(&b2[0]), b2v1 = __ldg(&b2[1]), b2v2 = __ldg(&b2[2]);
    __syncthreads();

    const int ntiles = (N_NODES + TN - 1) / TN;
    for (int t = blockIdx.x; t < ntiles; t += gridDim.x) {
        const int n0 = t * TN + w * 4;
#pragma unroll
        for (int i = 0; i < 4; i++) {
            int n = n0 + i;
            float4 hv = make_float4(0.f, 0.f, 0.f, 0.f);
            if (n < N_NODES)
                hv = *reinterpret_cast<const float4*>(g_h + (size_t)n * H + lane * 4);
            *reinterpret_cast<float4*>(sH + (w * 4 + i) * H + lane * 4) = hv;
        }
        __syncwarp();

        float acc[4][4];
#pragma unroll
        for (int i = 0; i < 4; i++) {
            acc[i][0] = b1v[0]; acc[i][1] = b1v[1];
            acc[i][2] = b1v[2]; acc[i][3] = b1v[3];
        }
#pragma unroll 1
        for (int kc = 0; kc < H; kc += 4) {
            float4 a4[4];
#pragma unroll
            for (int i = 0; i < 4; i++)
                a4[i] = *reinterpret_cast<const float4*>(sH + (w * 4 + i) * H + kc);
#pragma unroll
            for (int kk = 0; kk < 4; kk++) {
                float4 bv = *reinterpret_cast<const float4*>(sW1 + (kc + kk) * H + lane * 4);
#pragma unroll
                for (int i = 0; i < 4; i++) {
                    float a = (kk == 0) ? a4[i].x : (kk == 1) ? a4[i].y
                             : (kk == 2) ? a4[i].z : a4[i].w;
                    acc[i][0] = fmaf(a, bv.x, acc[i][0]);
                    acc[i][1] = fmaf(a, bv.y, acc[i][1]);
                    acc[i][2] = fmaf(a, bv.z, acc[i][2]);
                    acc[i][3] = fmaf(a, bv.w, acc[i][3]);
                }
            }
        }

#pragma unroll
        for (int i = 0; i < 4; i++) {
            float p0 = 0.f, p1 = 0.f, p2 = 0.f;
#pragma unroll
            for (int j = 0; j < 4; j++) {
                float o = fmaxf(acc[i][j], 0.f);
                int kk = lane * 4 + j;
                p0 = fmaf(o, sW2[kk * N_OUT + 0], p0);
                p1 = fmaf(o, sW2[kk * N_OUT + 1], p1);
                p2 = fmaf(o, sW2[kk * N_OUT + 2], p2);
            }
#pragma unroll
            for (int off = 16; off > 0; off >>= 1) {
                p0 += __shfl_xor_sync(0xffffffffu, p0, off);
                p1 += __shfl_xor_sync(0xffffffffu, p1, off);
                p2 += __shfl_xor_sync(0xffffffffu, p2, off);
            }
            int n = n0 + i;
            if (lane == 0 && n < N_NODES) {
                out[(size_t)n * N_OUT + 0] = fmaxf(p0 + b2v0, 0.f);
                out[(size_t)n * N_OUT + 1] = fmaxf(p1 + b2v1, 0.f);
                out[(size_t)n * N_OUT + 2] = fmaxf(p2 + b2v2, 0.f);
            }
        }
        __syncwarp();
    }
}

// ======================= launch ============================================

extern "C" void kernel_launch(void* const* d_in, const int* in_sizes, int n_in,
                              void* d_out, int out_size) {
    const float* x       = (const float*)d_in[0];
    const int*   ei      = (const int*)d_in[1];
    const float* ea      = (const float*)d_in[2];
    const float* lin_w   = (const float*)d_in[3];
    const float* lin_b   = (const float*)d_in[4];
    const float* msg_w1  = (const float*)d_in[5];
    const float* msg_b1  = (const float*)d_in[6];
    const float* msg_w2  = (const float*)d_in[7];
    const float* msg_b2  = (const float*)d_in[8];
    const float* upd_w1  = (const float*)d_in[9];
    const float* upd_b1  = (const float*)d_in[10];
    const float* upd_w2  = (const float*)d_in[11];
    const float* upd_b2  = (const float*)d_in[12];
    const float* head_w1 = (const float*)d_in[13];
    const float* head_b1 = (const float*)d_in[14];
    const float* head_w2 = (const float*)d_in[15];
    const float* head_b2 = (const float*)d_in[16];
    float* out = (float*)d_out;

    const int* src = ei;
    const int* dst = ei + N_EDGES;

    int sm_count = 148;
    cudaDeviceGetAttribute(&sm_count, cudaDevAttrMultiProcessorCount, 0);

    const size_t smHd = (size_t)(H * H + H * N_OUT + TN * H) * sizeof(float);
    cudaFuncSetAttribute(edge_kernel, cudaFuncAttributeMaxDynamicSharedMemorySize, SM_EDGE_TOTAL);
    cudaFuncSetAttribute(node_kernel, cudaFuncAttributeMaxDynamicSharedMemorySize, NB_TOTAL);
    cudaFuncSetAttribute(head_kernel, cudaFuncAttributeMaxDynamicSharedMemorySize, (int)smHd);

    zero_cnt_kernel<<<(N_NODES + 255) / 256, 256>>>();
    deg_kernel<<<(N_EDGES + 255) / 256, 256>>>(dst);
    inv_kernel<<<(N_NODES + 255) / 256, 256>>>();
    lin_in_kernel<<<N_NODES, H>>>(x, lin_w, lin_b);
    pack_ea_kernel<<<(N_EDGES + 255) / 256, 256>>>(ea);
    zero_agg_kernel<<<1024, 256>>>();   // layer 0 only; node_kernel zeroes thereafter

    for (int l = 0; l < N_LAYERS; l++) {
        edge_kernel<<<sm_count, 256, SM_EDGE_TOTAL>>>(
            src, dst,
            msg_w1 + (size_t)l * (H + ED) * H, msg_b1 + (size_t)l * H,
            msg_w2 + (size_t)l * H * H, msg_b2 + (size_t)l * H);
        node_kernel<<<sm_count, 256, NB_TOTAL>>>(
            upd_w1 + (size_t)l * 2 * H * H, upd_b1 + (size_t)l * H,
            upd_w2 + (size_t)l * H * H, upd_b2 + (size_t)l * H);
    }

    head_kernel<<<2 * sm_count, 256, smHd>>>(head_w1, head_b1, head_w2, head_b2, out);
}